// round 2
// baseline (speedup 1.0000x reference)
#include <cuda_runtime.h>

// Self_Attention: x[B,C,H,W], 1x1-conv projections q,k (D=32), v (C),
// energy = q^T k, softmax over j, out = V @ attn^T, final = gamma*out + x.
#define BB 4
#define CC_ 256
#define NN 4096
#define DD 32
#define ROWS 320  // 32 q + 32 k + 256 v

// Scratch (device globals; no runtime allocation allowed)
__device__ float g_qkv[BB][ROWS][NN];             // ~21 MB
__device__ float g_attn[(size_t)BB * NN * NN];    // 268 MB

// ---------------------------------------------------------------------------
// Kernel A: fused QKV projection.  [320 x 256] @ [256 x 4096] per batch.
// grid (64 n-tiles, 4 b), 256 threads. Each block: 64 tokens x 320 rows.
// ---------------------------------------------------------------------------
__global__ __launch_bounds__(256) void qkv_kernel(
    const float* __restrict__ x,
    const float* __restrict__ wq, const float* __restrict__ bq,
    const float* __restrict__ wk, const float* __restrict__ bk,
    const float* __restrict__ wv, const float* __restrict__ bv)
{
    __shared__ float xs[128][65];
    const int b  = blockIdx.y;
    const int n0 = blockIdx.x * 64;
    const int tid = threadIdx.x;
    const int tg = tid & 7;    // token group (8 tokens each)
    const int rg = tid >> 3;   // row group (10 rows each, 32 groups)
    const int t0 = tg * 8;

    float acc[10][8];
#pragma unroll
    for (int r = 0; r < 10; r++)
#pragma unroll
        for (int t = 0; t < 8; t++) acc[r][t] = 0.f;

    const float* wrow[10];
    float bias[10];
#pragma unroll
    for (int rr = 0; rr < 10; rr++) {
        int r = rg * 10 + rr;
        if (r < 32)      { wrow[rr] = wq + r * CC_;        bias[rr] = bq[r]; }
        else if (r < 64) { wrow[rr] = wk + (r - 32) * CC_; bias[rr] = bk[r - 32]; }
        else             { wrow[rr] = wv + (r - 64) * CC_; bias[rr] = bv[r - 64]; }
    }

    for (int half = 0; half < 2; half++) {
        for (int idx = tid; idx < 128 * 64; idx += 256) {
            int cc = idx >> 6, t = idx & 63;
            xs[cc][t] = x[((size_t)(b * CC_ + half * 128 + cc)) * NN + n0 + t];
        }
        __syncthreads();
#pragma unroll 4
        for (int cc = 0; cc < 128; cc++) {
            float xv[8];
#pragma unroll
            for (int t = 0; t < 8; t++) xv[t] = xs[cc][t0 + t];
#pragma unroll
            for (int rr = 0; rr < 10; rr++) {
                float w = wrow[rr][half * 128 + cc];
#pragma unroll
                for (int t = 0; t < 8; t++) acc[rr][t] = fmaf(w, xv[t], acc[rr][t]);
            }
        }
        __syncthreads();
    }

#pragma unroll
    for (int rr = 0; rr < 10; rr++) {
        int r = rg * 10 + rr;
        float* o = &g_qkv[b][r][n0 + t0];
#pragma unroll
        for (int t = 0; t < 8; t++) o[t] = acc[rr][t] + bias[rr];
    }
}

// ---------------------------------------------------------------------------
// Kernel B: energy[b,i,j] = sum_d q[b,d,i]*k[b,d,j].  64x64 tile per block.
// grid (64 j, 64 i, 4 b), 256 threads, 4x4 micro-tile.
// ---------------------------------------------------------------------------
__global__ __launch_bounds__(256) void energy_kernel()
{
    const int b  = blockIdx.z;
    const int i0 = blockIdx.y * 64;
    const int j0 = blockIdx.x * 64;
    __shared__ float qs[DD][64];
    __shared__ float ks[DD][64];
    const int tid = threadIdx.x;

    for (int idx = tid; idx < DD * 64; idx += 256) {
        int d = idx >> 6, t = idx & 63;
        qs[d][t] = g_qkv[b][d][i0 + t];
        ks[d][t] = g_qkv[b][32 + d][j0 + t];
    }
    __syncthreads();

    const int tx = tid & 15;   // j group
    const int ty = tid >> 4;   // i group
    float acc[4][4] = {};
#pragma unroll
    for (int d = 0; d < DD; d++) {
        float4 qv = *(const float4*)&qs[d][ty * 4];
        float4 kv = *(const float4*)&ks[d][tx * 4];
        const float qa[4] = {qv.x, qv.y, qv.z, qv.w};
        const float ka[4] = {kv.x, kv.y, kv.z, kv.w};
#pragma unroll
        for (int ii = 0; ii < 4; ii++)
#pragma unroll
            for (int jj = 0; jj < 4; jj++)
                acc[ii][jj] = fmaf(qa[ii], ka[jj], acc[ii][jj]);
    }

#pragma unroll
    for (int ii = 0; ii < 4; ii++) {
        size_t o = ((size_t)b * NN + (i0 + ty * 4 + ii)) * NN + j0 + tx * 4;
        float4 r = make_float4(acc[ii][0], acc[ii][1], acc[ii][2], acc[ii][3]);
        *(float4*)&g_attn[o] = r;
    }
}

// ---------------------------------------------------------------------------
// Kernel C: row softmax over j (length 4096).  One block per (b,i) row.
// ---------------------------------------------------------------------------
__global__ __launch_bounds__(256) void softmax_kernel()
{
    const size_t row = blockIdx.x;
    float* p = g_attn + row * (size_t)NN;
    const int tid = threadIdx.x;

    float4 v[4];
    float m = -1e30f;
#pragma unroll
    for (int l = 0; l < 4; l++) {
        v[l] = *(const float4*)&p[(tid + l * 256) * 4];
        m = fmaxf(m, fmaxf(fmaxf(v[l].x, v[l].y), fmaxf(v[l].z, v[l].w)));
    }
    __shared__ float redm[8], reds[8];
#pragma unroll
    for (int o = 16; o; o >>= 1) m = fmaxf(m, __shfl_xor_sync(0xffffffffu, m, o));
    if ((tid & 31) == 0) redm[tid >> 5] = m;
    __syncthreads();
    m = redm[0];
#pragma unroll
    for (int w = 1; w < 8; w++) m = fmaxf(m, redm[w]);

    float s = 0.f;
#pragma unroll
    for (int l = 0; l < 4; l++) {
        v[l].x = __expf(v[l].x - m);
        v[l].y = __expf(v[l].y - m);
        v[l].z = __expf(v[l].z - m);
        v[l].w = __expf(v[l].w - m);
        s += v[l].x + v[l].y + v[l].z + v[l].w;
    }
#pragma unroll
    for (int o = 16; o; o >>= 1) s += __shfl_xor_sync(0xffffffffu, s, o);
    if ((tid & 31) == 0) reds[tid >> 5] = s;
    __syncthreads();
    s = 0.f;
#pragma unroll
    for (int w = 0; w < 8; w++) s += reds[w];
    const float inv = 1.0f / s;

#pragma unroll
    for (int l = 0; l < 4; l++) {
        v[l].x *= inv; v[l].y *= inv; v[l].z *= inv; v[l].w *= inv;
        *(float4*)&p[(tid + l * 256) * 4] = v[l];
    }
}

// ---------------------------------------------------------------------------
// Kernel D: out[b,c,i] = sum_j V[b,c,j]*attn[b,i,j];  final = gamma*out + x.
// 128c x 128i tile per block, k-chunk 16, 8x8 micro-tile.
// grid (32 i, 2 c, 4 b), 256 threads.
// ---------------------------------------------------------------------------
__global__ __launch_bounds__(256) void out_kernel(
    const float* __restrict__ x, const float* __restrict__ gamma_p,
    float* __restrict__ out)
{
    const int b  = blockIdx.z;
    const int c0 = blockIdx.y * 128;
    const int i0 = blockIdx.x * 128;
    __shared__ float As[16][132];  // [j][i]
    __shared__ float Vs[16][132];  // [j][c]
    const int tid = threadIdx.x;
    const int tx = tid & 15;   // c group (8 channels)
    const int ty = tid >> 4;   // i group (8 tokens)

    const float* Abase = g_attn + ((size_t)b * NN + i0) * NN;
    const float* Vbase = &g_qkv[b][64 + c0][0];

    float acc[8][8] = {};

    for (int j0 = 0; j0 < NN; j0 += 16) {
#pragma unroll
        for (int l = 0; l < 2; l++) {
            int lin = (tid + l * 256) * 4;
            int r  = lin >> 4;     // row within 128 (i for A, c for V)
            int jj = lin & 15;     // j offset (multiple of 4)
            float4 a = *(const float4*)&Abase[(size_t)r * NN + j0 + jj];
            As[jj + 0][r] = a.x; As[jj + 1][r] = a.y;
            As[jj + 2][r] = a.z; As[jj + 3][r] = a.w;
            float4 vv = *(const float4*)&Vbase[(size_t)r * NN + j0 + jj];
            Vs[jj + 0][r] = vv.x; Vs[jj + 1][r] = vv.y;
            Vs[jj + 2][r] = vv.z; Vs[jj + 3][r] = vv.w;
        }
        __syncthreads();
#pragma unroll
        for (int j = 0; j < 16; j++) {
            float af[8], vf[8];
            *(float4*)&af[0] = *(const float4*)&As[j][ty * 8];
            *(float4*)&af[4] = *(const float4*)&As[j][ty * 8 + 4];
            *(float4*)&vf[0] = *(const float4*)&Vs[j][tx * 8];
            *(float4*)&vf[4] = *(const float4*)&Vs[j][tx * 8 + 4];
#pragma unroll
            for (int ii = 0; ii < 8; ii++)
#pragma unroll
                for (int cc = 0; cc < 8; cc++)
                    acc[ii][cc] = fmaf(af[ii], vf[cc], acc[ii][cc]);
        }
        __syncthreads();
    }

    const float g = gamma_p[0];
#pragma unroll
    for (int cc = 0; cc < 8; cc++) {
        size_t o = ((size_t)(b * CC_ + c0 + tx * 8 + cc)) * NN + i0 + ty * 8;
        float4 x0 = *(const float4*)&x[o];
        float4 x1 = *(const float4*)&x[o + 4];
        float4 r0 = make_float4(fmaf(g, acc[0][cc], x0.x), fmaf(g, acc[1][cc], x0.y),
                                fmaf(g, acc[2][cc], x0.z), fmaf(g, acc[3][cc], x0.w));
        float4 r1 = make_float4(fmaf(g, acc[4][cc], x1.x), fmaf(g, acc[5][cc], x1.y),
                                fmaf(g, acc[6][cc], x1.z), fmaf(g, acc[7][cc], x1.w));
        *(float4*)&out[o]     = r0;
        *(float4*)&out[o + 4] = r1;
    }
}

// ---------------------------------------------------------------------------
extern "C" void kernel_launch(void* const* d_in, const int* in_sizes, int n_in,
                              void* d_out, int out_size)
{
    const float* x     = (const float*)d_in[0];
    const float* wq    = (const float*)d_in[1];
    const float* bq    = (const float*)d_in[2];
    const float* wk    = (const float*)d_in[3];
    const float* bk    = (const float*)d_in[4];
    const float* wv    = (const float*)d_in[5];
    const float* bv    = (const float*)d_in[6];
    const float* gamma = (const float*)d_in[7];
    float* out = (float*)d_out;

    qkv_kernel<<<dim3(64, 4), 256>>>(x, wq, bq, wk, bk, wv, bv);
    energy_kernel<<<dim3(64, 64, 4), 256>>>();
    softmax_kernel<<<dim3(BB * NN), 256>>>();
    out_kernel<<<dim3(32, 2, 4), 256>>>(x, gamma, out);
}

// round 4
// speedup vs baseline: 2.6493x; 2.6493x over previous
#include <cuda_runtime.h>
#include <cuda_bf16.h>
#include <cstdint>

// Self_Attention: x[B,C,H,W], 1x1-conv projections q,k (D=32), v (C),
// energy = q^T k, softmax over j, out = V @ attn^T, final = gamma*out + x.
// NOTE: harness PTX target is plain sm_103 (no 'a') -> tcgen05/TMEM are
// unavailable; tensor work uses mma.sync (HMMA) + ldmatrix + cp.async.
#define BB 4
#define CC_ 256
#define NN 4096
#define DD 32

// Scratch (device globals; no runtime allocation allowed)
__device__ float g_qkv[BB][64][NN];                       // q,k fp32 (~4 MB)
__device__ float g_attn[(size_t)BB * NN * NN];            // energy fp32, 268 MB
__device__ __nv_bfloat16 g_attn16[(size_t)BB * NN * NN];  // probs bf16, 134 MB
__device__ __nv_bfloat16 g_v16[BB][CC_][NN];              // V bf16, 8 MB

__device__ __forceinline__ uint32_t smem_u32(const void* p) {
    uint32_t a;
    asm("{ .reg .u64 t; cvta.to.shared.u64 t, %1; cvt.u32.u64 %0, t; }" : "=r"(a) : "l"(p));
    return a;
}

#define CP_ASYNC16(dst, src) \
    asm volatile("cp.async.cg.shared.global [%0], [%1], 16;" :: "r"(dst), "l"(src))
#define CP_COMMIT()  asm volatile("cp.async.commit_group;")
#define CP_WAIT1()   asm volatile("cp.async.wait_group 1;")
#define CP_WAIT0()   asm volatile("cp.async.wait_group 0;")

#define LDMATRIX_X4(r0, r1, r2, r3, addr)                                          \
    asm volatile("ldmatrix.sync.aligned.m8n8.x4.shared.b16 {%0,%1,%2,%3}, [%4];"   \
        : "=r"(r0), "=r"(r1), "=r"(r2), "=r"(r3) : "r"(addr))

#define MMA16816(c, a, b)                                                          \
    asm volatile("mma.sync.aligned.m16n8k16.row.col.f32.bf16.bf16.f32 "            \
        "{%0,%1,%2,%3}, {%4,%5,%6,%7}, {%8,%9}, {%0,%1,%2,%3};"                    \
        : "+f"((c)[0]), "+f"((c)[1]), "+f"((c)[2]), "+f"((c)[3])                   \
        : "r"((a)[0]), "r"((a)[1]), "r"((a)[2]), "r"((a)[3]),                      \
          "r"((b)[0]), "r"((b)[1]))

// ---------------------------------------------------------------------------
// Kernel A: fused QKV projection. q,k -> fp32 g_qkv; v -> bf16 g_v16.
// ---------------------------------------------------------------------------
__global__ __launch_bounds__(256) void qkv_kernel(
    const float* __restrict__ x,
    const float* __restrict__ wq, const float* __restrict__ bq,
    const float* __restrict__ wk, const float* __restrict__ bk,
    const float* __restrict__ wv, const float* __restrict__ bv)
{
    __shared__ float xs[128][65];
    const int b  = blockIdx.y;
    const int n0 = blockIdx.x * 64;
    const int tid = threadIdx.x;
    const int tg = tid & 7;
    const int rg = tid >> 3;
    const int t0 = tg * 8;

    float acc[10][8];
#pragma unroll
    for (int r = 0; r < 10; r++)
#pragma unroll
        for (int t = 0; t < 8; t++) acc[r][t] = 0.f;

    const float* wrow[10];
    float bias[10];
#pragma unroll
    for (int rr = 0; rr < 10; rr++) {
        int r = rg * 10 + rr;
        if (r < 32)      { wrow[rr] = wq + r * CC_;        bias[rr] = bq[r]; }
        else if (r < 64) { wrow[rr] = wk + (r - 32) * CC_; bias[rr] = bk[r - 32]; }
        else             { wrow[rr] = wv + (r - 64) * CC_; bias[rr] = bv[r - 64]; }
    }

    for (int half = 0; half < 2; half++) {
        for (int idx = tid; idx < 128 * 64; idx += 256) {
            int cc = idx >> 6, t = idx & 63;
            xs[cc][t] = x[((size_t)(b * CC_ + half * 128 + cc)) * NN + n0 + t];
        }
        __syncthreads();
#pragma unroll 4
        for (int cc = 0; cc < 128; cc++) {
            float xv[8];
#pragma unroll
            for (int t = 0; t < 8; t++) xv[t] = xs[cc][t0 + t];
#pragma unroll
            for (int rr = 0; rr < 10; rr++) {
                float w = wrow[rr][half * 128 + cc];
#pragma unroll
                for (int t = 0; t < 8; t++) acc[rr][t] = fmaf(w, xv[t], acc[rr][t]);
            }
        }
        __syncthreads();
    }

#pragma unroll
    for (int rr = 0; rr < 10; rr++) {
        int r = rg * 10 + rr;
        if (r < 64) {
            float* o = &g_qkv[b][r][n0 + t0];
#pragma unroll
            for (int t = 0; t < 8; t++) o[t] = acc[rr][t] + bias[rr];
        } else {
            __nv_bfloat162 pk[4];
#pragma unroll
            for (int t = 0; t < 4; t++)
                pk[t] = __floats2bfloat162_rn(acc[rr][2 * t] + bias[rr],
                                              acc[rr][2 * t + 1] + bias[rr]);
            *(uint4*)&g_v16[b][r - 64][n0 + t0] = *(uint4*)pk;
        }
    }
}

// ---------------------------------------------------------------------------
// Kernel B: energy[b,i,j] = sum_d q[b,d,i]*k[b,d,j].
// ---------------------------------------------------------------------------
__global__ __launch_bounds__(256) void energy_kernel()
{
    const int b  = blockIdx.z;
    const int i0 = blockIdx.y * 64;
    const int j0 = blockIdx.x * 64;
    __shared__ float qs[DD][64];
    __shared__ float ks[DD][64];
    const int tid = threadIdx.x;

    for (int idx = tid; idx < DD * 64; idx += 256) {
        int d = idx >> 6, t = idx & 63;
        qs[d][t] = g_qkv[b][d][i0 + t];
        ks[d][t] = g_qkv[b][32 + d][j0 + t];
    }
    __syncthreads();

    const int tx = tid & 15;
    const int ty = tid >> 4;
    float acc[4][4] = {};
#pragma unroll
    for (int d = 0; d < DD; d++) {
        float4 qv = *(const float4*)&qs[d][ty * 4];
        float4 kv = *(const float4*)&ks[d][tx * 4];
        const float qa[4] = {qv.x, qv.y, qv.z, qv.w};
        const float ka[4] = {kv.x, kv.y, kv.z, kv.w};
#pragma unroll
        for (int ii = 0; ii < 4; ii++)
#pragma unroll
            for (int jj = 0; jj < 4; jj++)
                acc[ii][jj] = fmaf(qa[ii], ka[jj], acc[ii][jj]);
    }

#pragma unroll
    for (int ii = 0; ii < 4; ii++) {
        size_t o = ((size_t)b * NN + (i0 + ty * 4 + ii)) * NN + j0 + tx * 4;
        *(float4*)&g_attn[o] = make_float4(acc[ii][0], acc[ii][1], acc[ii][2], acc[ii][3]);
    }
}

// ---------------------------------------------------------------------------
// Kernel C: row softmax; reads fp32 energy, writes bf16 probs (halved writes).
// ---------------------------------------------------------------------------
__global__ __launch_bounds__(256) void softmax_kernel()
{
    const size_t row = blockIdx.x;
    const float* p = g_attn + row * (size_t)NN;
    __nv_bfloat16* p16 = g_attn16 + row * (size_t)NN;
    const int tid = threadIdx.x;

    float4 v[4];
    float m = -1e30f;
#pragma unroll
    for (int l = 0; l < 4; l++) {
        v[l] = *(const float4*)&p[(tid + l * 256) * 4];
        m = fmaxf(m, fmaxf(fmaxf(v[l].x, v[l].y), fmaxf(v[l].z, v[l].w)));
    }
    __shared__ float redm[8], reds[8];
#pragma unroll
    for (int o = 16; o; o >>= 1) m = fmaxf(m, __shfl_xor_sync(0xffffffffu, m, o));
    if ((tid & 31) == 0) redm[tid >> 5] = m;
    __syncthreads();
    m = redm[0];
#pragma unroll
    for (int w = 1; w < 8; w++) m = fmaxf(m, redm[w]);

    float s = 0.f;
#pragma unroll
    for (int l = 0; l < 4; l++) {
        v[l].x = __expf(v[l].x - m);
        v[l].y = __expf(v[l].y - m);
        v[l].z = __expf(v[l].z - m);
        v[l].w = __expf(v[l].w - m);
        s += v[l].x + v[l].y + v[l].z + v[l].w;
    }
#pragma unroll
    for (int o = 16; o; o >>= 1) s += __shfl_xor_sync(0xffffffffu, s, o);
    if ((tid & 31) == 0) reds[tid >> 5] = s;
    __syncthreads();
    s = 0.f;
#pragma unroll
    for (int w = 0; w < 8; w++) s += reds[w];
    const float inv = 1.0f / s;

#pragma unroll
    for (int l = 0; l < 4; l++) {
        __nv_bfloat162 o0 = __floats2bfloat162_rn(v[l].x * inv, v[l].y * inv);
        __nv_bfloat162 o1 = __floats2bfloat162_rn(v[l].z * inv, v[l].w * inv);
        __nv_bfloat162* o = (__nv_bfloat162*)(p16 + (size_t)(tid + l * 256) * 4);
        o[0] = o0;
        o[1] = o1;
    }
}

// ---------------------------------------------------------------------------
// Kernel D (HMMA): out[b,c,i] = sum_j V[b,c,j]*attn[b,i,j]; gamma*out + x.
// A = V [m=c][k=j] row-major, B = attn [n=i][k=j] (col-major for mma) -> both
// k-contiguous, mma.row.col. CTA tile 128(m) x 128(n), K-chunk 64, 8 warps
// (2m x 4n, 64x32 each), cp.async double buffer, pad-72 rows (conflict-free
// ldmatrix). grid (32 i, 2 c, 4 b), 256 threads, 73728 B dyn smem.
// ---------------------------------------------------------------------------
#define KC        64
#define RSTRIDE   144                  // bytes per smem row (64 bf16 + 8 pad)
#define OPBYTES   (128 * RSTRIDE)      // 18432
#define BUFBYTES  (2 * OPBYTES)        // 36864 (V + attn)
#define SMEM_D    (2 * BUFBYTES)       // 73728

__global__ __launch_bounds__(256, 1) void out_kernel_mma(
    const float* __restrict__ x, const float* __restrict__ gamma_p,
    float* __restrict__ out)
{
    extern __shared__ char smem[];
    const uint32_t sbase = smem_u32(smem);
    const int tid  = threadIdx.x;
    const int wid  = tid >> 5;
    const int lane = tid & 31;
    const int b  = blockIdx.z;
    const int c0 = blockIdx.y * 128;
    const int i0 = blockIdx.x * 128;

    const int m_base = (wid >> 2) * 64;   // warp's channel-row offset
    const int n_base = (wid & 3) * 32;    // warp's token-col offset

    // Per-thread cp.async assignments: 2048 16B transfers / 256 threads = 8.
    // t = tid + p*256: op = t>>10 (0=V,1=attn), row = (t>>3)&127, seg = t&7.
    const __nv_bfloat16* Vg = &g_v16[b][c0][0];
    const __nv_bfloat16* Ag = g_attn16 + ((size_t)b * NN + i0) * NN;

    float c[4][4][4];
#pragma unroll
    for (int mt = 0; mt < 4; mt++)
#pragma unroll
        for (int nt = 0; nt < 4; nt++)
#pragma unroll
            for (int r = 0; r < 4; r++) c[mt][nt][r] = 0.f;

    // ---- chunk loader (cp.async) ----
    auto load_chunk = [&](int chunk) {
        const uint32_t dbuf = sbase + (uint32_t)(chunk & 1) * BUFBYTES;
        const int jel = chunk * KC;  // j element offset
#pragma unroll
        for (int p = 0; p < 8; p++) {
            int t = tid + p * 256;
            int op  = t >> 10;
            int row = (t >> 3) & 127;
            int seg = t & 7;
            uint32_t dst = dbuf + (uint32_t)op * OPBYTES + row * RSTRIDE + seg * 16;
            const __nv_bfloat16* src = op
                ? Ag + (size_t)row * NN + jel + seg * 8
                : Vg + (size_t)row * NN + jel + seg * 8;
            CP_ASYNC16(dst, src);
        }
        CP_COMMIT();
    };

    load_chunk(0);

    for (int chunk = 0; chunk < NN / KC; chunk++) {
        if (chunk + 1 < NN / KC) { load_chunk(chunk + 1); CP_WAIT1(); }
        else                     { CP_WAIT0(); }
        __syncthreads();

        const uint32_t aBase = sbase + (uint32_t)(chunk & 1) * BUFBYTES;          // V
        const uint32_t bBase = aBase + OPBYTES;                                    // attn
#pragma unroll
        for (int ks = 0; ks < KC / 16; ks++) {
            const int kb = ks * 32;  // byte offset of this k16 slice
            uint32_t a[4][4];
#pragma unroll
            for (int mt = 0; mt < 4; mt++) {
                uint32_t addr = aBase + (m_base + mt * 16 + (lane & 15)) * RSTRIDE
                              + kb + ((lane >> 4) << 4);
                LDMATRIX_X4(a[mt][0], a[mt][1], a[mt][2], a[mt][3], addr);
            }
            uint32_t bf[4][2];
#pragma unroll
            for (int bt = 0; bt < 2; bt++) {
                int row = n_base + bt * 16 + ((lane >> 4) << 3) + (lane & 7);
                uint32_t addr = bBase + row * RSTRIDE + kb + (((lane >> 3) & 1) << 4);
                uint32_t r0, r1, r2, r3;
                LDMATRIX_X4(r0, r1, r2, r3, addr);
                bf[bt * 2 + 0][0] = r0; bf[bt * 2 + 0][1] = r1;
                bf[bt * 2 + 1][0] = r2; bf[bt * 2 + 1][1] = r3;
            }
#pragma unroll
            for (int mt = 0; mt < 4; mt++)
#pragma unroll
                for (int nt = 0; nt < 4; nt++)
                    MMA16816(c[mt][nt], a[mt], bf[nt]);
        }
        __syncthreads();
    }

    // ---- epilogue: gamma*acc + x ----
    const float g = gamma_p[0];
    const int rquad = lane >> 2;        // 0..7
    const int cpair = (lane & 3) * 2;   // 0,2,4,6
#pragma unroll
    for (int mt = 0; mt < 4; mt++) {
#pragma unroll
        for (int half = 0; half < 2; half++) {
            int m = m_base + mt * 16 + rquad + half * 8;
            size_t rowoff = ((size_t)(b * CC_ + c0 + m)) * NN + i0;
#pragma unroll
            for (int nt = 0; nt < 4; nt++) {
                int n = n_base + nt * 8 + cpair;
                float2 xv = *(const float2*)&x[rowoff + n];
                float2 r;
                r.x = fmaf(g, c[mt][nt][half * 2 + 0], xv.x);
                r.y = fmaf(g, c[mt][nt][half * 2 + 1], xv.y);
                *(float2*)&out[rowoff + n] = r;
            }
        }
    }
}

// ---------------------------------------------------------------------------
extern "C" void kernel_launch(void* const* d_in, const int* in_sizes, int n_in,
                              void* d_out, int out_size)
{
    const float* x     = (const float*)d_in[0];
    const float* wq    = (const float*)d_in[1];
    const float* bq    = (const float*)d_in[2];
    const float* wk    = (const float*)d_in[3];
    const float* bk    = (const float*)d_in[4];
    const float* wv    = (const float*)d_in[5];
    const float* bv    = (const float*)d_in[6];
    const float* gamma = (const float*)d_in[7];
    float* out = (float*)d_out;

    cudaFuncSetAttribute(out_kernel_mma, cudaFuncAttributeMaxDynamicSharedMemorySize, SMEM_D);

    qkv_kernel<<<dim3(64, 4), 256>>>(x, wq, bq, wk, bk, wv, bv);
    energy_kernel<<<dim3(64, 64, 4), 256>>>();
    softmax_kernel<<<dim3(BB * NN), 256>>>();
    out_kernel_mma<<<dim3(32, 2, 4), 256, SMEM_D>>>(x, gamma, out);
}

// round 5
// speedup vs baseline: 3.3751x; 1.2739x over previous
#include <cuda_runtime.h>
#include <cuda_bf16.h>
#include <cstdint>

// Self_Attention: x[B,C,H,W], 1x1-conv projections q,k (D=32), v (C),
// energy = q^T k, softmax over j, out = V @ attn^T, final = gamma*out + x.
// Plain-sm_103 PTX target -> no tcgen05; HMMA (mma.sync) + ldmatrix + cp.async.
#define BB 4
#define CC_ 256
#define NN 4096
#define DD 32

// Scratch (device globals; no runtime allocation allowed)
__device__ __nv_bfloat16 g_attn16[(size_t)BB * NN * NN];  // unnorm exp probs, 134 MB
__device__ __nv_bfloat16 g_v16[BB][CC_][NN];              // V bf16, 8 MB
__device__ __nv_bfloat16 g_qk16[BB][64][NN];              // q,k bf16 d-major, 2 MB
__device__ __nv_bfloat16 g_qT[BB][NN][DD];                // q bf16 token-major, 1 MB
__device__ __nv_bfloat16 g_kT[BB][NN][DD];                // k bf16 token-major, 1 MB
__device__ float g_invs[BB][NN];                          // 1/rowsum, 64 KB

__device__ __forceinline__ uint32_t smem_u32(const void* p) {
    uint32_t a;
    asm("{ .reg .u64 t; cvta.to.shared.u64 t, %1; cvt.u32.u64 %0, t; }" : "=r"(a) : "l"(p));
    return a;
}

#define CP_ASYNC16(dst, src) \
    asm volatile("cp.async.cg.shared.global [%0], [%1], 16;" :: "r"(dst), "l"(src))
#define CP_COMMIT()  asm volatile("cp.async.commit_group;")
#define CP_WAIT1()   asm volatile("cp.async.wait_group 1;")
#define CP_WAIT0()   asm volatile("cp.async.wait_group 0;")

#define LDMATRIX_X4(r0, r1, r2, r3, addr)                                          \
    asm volatile("ldmatrix.sync.aligned.m8n8.x4.shared.b16 {%0,%1,%2,%3}, [%4];"   \
        : "=r"(r0), "=r"(r1), "=r"(r2), "=r"(r3) : "r"(addr))

#define MMA16816(c, a, b)                                                          \
    asm volatile("mma.sync.aligned.m16n8k16.row.col.f32.bf16.bf16.f32 "            \
        "{%0,%1,%2,%3}, {%4,%5,%6,%7}, {%8,%9}, {%0,%1,%2,%3};"                    \
        : "+f"((c)[0]), "+f"((c)[1]), "+f"((c)[2]), "+f"((c)[3])                   \
        : "r"((a)[0]), "r"((a)[1]), "r"((a)[2]), "r"((a)[3]),                      \
          "r"((b)[0]), "r"((b)[1]))

// ---------------------------------------------------------------------------
// Kernel A: fused QKV projection. q,k -> bf16 g_qk16 (d-major); v -> g_v16.
// ---------------------------------------------------------------------------
__global__ __launch_bounds__(256) void qkv_kernel(
    const float* __restrict__ x,
    const float* __restrict__ wq, const float* __restrict__ bq,
    const float* __restrict__ wk, const float* __restrict__ bk,
    const float* __restrict__ wv, const float* __restrict__ bv)
{
    __shared__ float xs[128][65];
    const int b  = blockIdx.y;
    const int n0 = blockIdx.x * 64;
    const int tid = threadIdx.x;
    const int tg = tid & 7;
    const int rg = tid >> 3;
    const int t0 = tg * 8;

    float acc[10][8];
#pragma unroll
    for (int r = 0; r < 10; r++)
#pragma unroll
        for (int t = 0; t < 8; t++) acc[r][t] = 0.f;

    const float* wrow[10];
    float bias[10];
#pragma unroll
    for (int rr = 0; rr < 10; rr++) {
        int r = rg * 10 + rr;
        if (r < 32)      { wrow[rr] = wq + r * CC_;        bias[rr] = bq[r]; }
        else if (r < 64) { wrow[rr] = wk + (r - 32) * CC_; bias[rr] = bk[r - 32]; }
        else             { wrow[rr] = wv + (r - 64) * CC_; bias[rr] = bv[r - 64]; }
    }

    for (int half = 0; half < 2; half++) {
        for (int idx = tid; idx < 128 * 64; idx += 256) {
            int cc = idx >> 6, t = idx & 63;
            xs[cc][t] = x[((size_t)(b * CC_ + half * 128 + cc)) * NN + n0 + t];
        }
        __syncthreads();
#pragma unroll 4
        for (int cc = 0; cc < 128; cc++) {
            float xv[8];
#pragma unroll
            for (int t = 0; t < 8; t++) xv[t] = xs[cc][t0 + t];
#pragma unroll
            for (int rr = 0; rr < 10; rr++) {
                float w = wrow[rr][half * 128 + cc];
#pragma unroll
                for (int t = 0; t < 8; t++) acc[rr][t] = fmaf(w, xv[t], acc[rr][t]);
            }
        }
        __syncthreads();
    }

#pragma unroll
    for (int rr = 0; rr < 10; rr++) {
        int r = rg * 10 + rr;
        __nv_bfloat162 pk[4];
#pragma unroll
        for (int t = 0; t < 4; t++)
            pk[t] = __floats2bfloat162_rn(acc[rr][2 * t] + bias[rr],
                                          acc[rr][2 * t + 1] + bias[rr]);
        if (r < 64) *(uint4*)&g_qk16[b][r][n0 + t0]      = *(uint4*)pk;
        else        *(uint4*)&g_v16[b][r - 64][n0 + t0]  = *(uint4*)pk;
    }
}

// ---------------------------------------------------------------------------
// Kernel T: transpose q,k from [d][n] to token-major [n][32] bf16.
// grid (128 token-tiles, 2 sel, 4 b), block (32,8).
// ---------------------------------------------------------------------------
__global__ __launch_bounds__(256) void transpose_qk()
{
    __shared__ __nv_bfloat16 ts[32][33];
    const int b   = blockIdx.z;
    const int sel = blockIdx.y;           // 0 = q, 1 = k
    const int t0  = blockIdx.x * 32;
    const int tx  = threadIdx.x, ty = threadIdx.y;

#pragma unroll
    for (int yy = ty; yy < 32; yy += 8)
        ts[yy][tx] = g_qk16[b][sel * 32 + yy][t0 + tx];
    __syncthreads();

    __nv_bfloat16* outp = sel ? &g_kT[b][0][0] : &g_qT[b][0][0];
#pragma unroll
    for (int yy = ty; yy < 32; yy += 8)
        outp[(size_t)(t0 + yy) * DD + tx] = ts[tx][yy];
}

// ---------------------------------------------------------------------------
// Kernel E (fused energy+softmax, HMMA): for each row i, over all j:
//   S = q_i . k_j  (bf16 HMMA, K=32), p' = exp(S) (no max; |S| <~ 40 safe),
//   write p' bf16 to g_attn16, accumulate rowsum -> g_invs = 1/s.
// CTA: 64 i x 4096 j. 8 warps: mq=wid&3 -> 16 i-rows; jh=wid>>2 -> 64-j half.
// j-chunk 128, cp.async double buffer. XOR-swizzled smem stage for coalesced
// global writes. grid (64, 4), 256 threads.
// ---------------------------------------------------------------------------
#define TI 64
#define TJ 128
#define QS_OFF  0               // 64 rows x 80 B
#define KS_OFF  5120            // 2 x 128 x 80 B
#define KS_BUF  10240
#define ST_OFF  25600           // 64 rows x 256 B stage
#define ESM_SZ  41984

__global__ __launch_bounds__(256) void energy_softmax_kernel()
{
    __shared__ char esm[ESM_SZ];
    __shared__ float rsum[2][TI];
    const uint32_t sb = smem_u32(esm);
    const int tid = threadIdx.x;
    const int wid = tid >> 5, lane = tid & 31;
    const int mq = wid & 3;          // 16 i-rows: mq*16..+15
    const int jh = wid >> 2;         // j half within chunk: jh*64..+63
    const int b  = blockIdx.y;
    const int i0 = blockIdx.x * TI;

    // q tile: 64 rows x 64 B (+16 pad) ; one 16B cp.async per thread
    {
        int row = tid >> 2, seg = tid & 3;
        CP_ASYNC16(sb + QS_OFF + row * 80 + seg * 16, &g_qT[b][i0 + row][seg * 8]);
    }
    // k chunk 0
    {
#pragma unroll
        for (int p = 0; p < 2; p++) {
            int idx = tid + p * 256;
            int row = idx >> 2, seg = idx & 3;
            CP_ASYNC16(sb + KS_OFF + row * 80 + seg * 16, &g_kT[b][row][seg * 8]);
        }
    }
    CP_COMMIT();

    float sum0 = 0.f, sum1 = 0.f;
    const int r = lane >> 2;
    const int rowA = mq * 16 + r, rowB = rowA + 8;

    for (int c = 0; c < NN / TJ; c++) {
        if (c + 1 < NN / TJ) {
#pragma unroll
            for (int p = 0; p < 2; p++) {
                int idx = tid + p * 256;
                int row = idx >> 2, seg = idx & 3;
                CP_ASYNC16(sb + KS_OFF + ((c + 1) & 1) * KS_BUF + row * 80 + seg * 16,
                           &g_kT[b][(c + 1) * TJ + row][seg * 8]);
            }
            CP_COMMIT();
            CP_WAIT1();
        } else {
            CP_WAIT0();
        }
        __syncthreads();   // k chunk visible; stage free (prev global reads done)

        const uint32_t ksb = sb + KS_OFF + (c & 1) * KS_BUF;
        float cc[8][4];
#pragma unroll
        for (int nt = 0; nt < 8; nt++)
#pragma unroll
            for (int q = 0; q < 4; q++) cc[nt][q] = 0.f;

#pragma unroll
        for (int ks = 0; ks < 2; ks++) {
            const int kb = ks * 32;
            uint32_t a[4];
            {
                uint32_t addr = sb + QS_OFF + (mq * 16 + (lane & 15)) * 80 + kb
                              + ((lane >> 4) << 4);
                LDMATRIX_X4(a[0], a[1], a[2], a[3], addr);
            }
            uint32_t bf[8][2];
#pragma unroll
            for (int bt = 0; bt < 4; bt++) {
                int row = jh * 64 + bt * 16 + ((lane >> 4) << 3) + (lane & 7);
                uint32_t addr = ksb + row * 80 + kb + (((lane >> 3) & 1) << 4);
                uint32_t r0, r1, r2, r3;
                LDMATRIX_X4(r0, r1, r2, r3, addr);
                bf[bt * 2 + 0][0] = r0; bf[bt * 2 + 0][1] = r1;
                bf[bt * 2 + 1][0] = r2; bf[bt * 2 + 1][1] = r3;
            }
#pragma unroll
            for (int nt = 0; nt < 8; nt++) MMA16816(cc[nt], a, bf[nt]);
        }

        // exp + rowsum + swizzled stage store
#pragma unroll
        for (int nt = 0; nt < 8; nt++) {
            float e0 = __expf(cc[nt][0]);
            float e1 = __expf(cc[nt][1]);
            float e2 = __expf(cc[nt][2]);
            float e3 = __expf(cc[nt][3]);
            sum0 += e0 + e1;
            sum1 += e2 + e3;
            int cell = jh * 8 + nt;
            __nv_bfloat162 pA = __floats2bfloat162_rn(e0, e1);
            __nv_bfloat162 pB = __floats2bfloat162_rn(e2, e3);
            *(uint32_t*)(esm + ST_OFF + rowA * 256 + ((cell ^ (rowA & 15)) << 4)
                         + (lane & 3) * 4) = *(uint32_t*)&pA;
            *(uint32_t*)(esm + ST_OFF + rowB * 256 + ((cell ^ (rowB & 15)) << 4)
                         + (lane & 3) * 4) = *(uint32_t*)&pB;
        }
        __syncthreads();

        // coalesced global write: 4 cells (16B each) per thread, same row
        __nv_bfloat16* Gp = g_attn16 + ((size_t)b * NN + i0) * NN + c * TJ;
        {
            int linear = tid * 4;
            int row = linear >> 4;
            int cl0 = linear & 15;
#pragma unroll
            for (int q = 0; q < 4; q++) {
                int cell = cl0 + q;
                uint4 v = *(uint4*)(esm + ST_OFF + row * 256
                                    + ((cell ^ (row & 15)) << 4));
                *(uint4*)(Gp + (size_t)row * NN + cell * 8) = v;
            }
        }
        __syncthreads();
    }

    // reduce rowsums: quad lanes hold same rows
    sum0 += __shfl_xor_sync(0xffffffffu, sum0, 1);
    sum0 += __shfl_xor_sync(0xffffffffu, sum0, 2);
    sum1 += __shfl_xor_sync(0xffffffffu, sum1, 1);
    sum1 += __shfl_xor_sync(0xffffffffu, sum1, 2);
    if ((lane & 3) == 0) {
        rsum[jh][rowA] = sum0;
        rsum[jh][rowB] = sum1;
    }
    __syncthreads();
    if (tid < TI)
        g_invs[b][i0 + tid] = 1.0f / (rsum[0][tid] + rsum[1][tid]);
}

// ---------------------------------------------------------------------------
// Kernel D (HMMA): out[b,c,i] = inv_s[i] * sum_j V[c,j]*p'[i,j]; gamma*.+x.
// CTA tile 128(m=c) x 128(n=i), K-chunk 64, 8 warps (2m x 4n), cp.async
// double buffer, pad-72 rows. grid (32 i, 2 c, 4 b), 256 thr, 73728 B smem.
// ---------------------------------------------------------------------------
#define KC        64
#define RSTRIDE   144
#define OPBYTES   (128 * RSTRIDE)
#define BUFBYTES  (2 * OPBYTES)
#define SMEM_D    (2 * BUFBYTES)

__global__ __launch_bounds__(256, 1) void out_kernel_mma(
    const float* __restrict__ x, const float* __restrict__ gamma_p,
    float* __restrict__ out)
{
    extern __shared__ char smem[];
    __shared__ float invs[128];
    const uint32_t sbase = smem_u32(smem);
    const int tid  = threadIdx.x;
    const int wid  = tid >> 5;
    const int lane = tid & 31;
    const int b  = blockIdx.z;
    const int c0 = blockIdx.y * 128;
    const int i0 = blockIdx.x * 128;

    if (tid < 128) invs[tid] = g_invs[b][i0 + tid];

    const int m_base = (wid >> 2) * 64;
    const int n_base = (wid & 3) * 32;

    const __nv_bfloat16* Vg = &g_v16[b][c0][0];
    const __nv_bfloat16* Ag = g_attn16 + ((size_t)b * NN + i0) * NN;

    float c[4][4][4];
#pragma unroll
    for (int mt = 0; mt < 4; mt++)
#pragma unroll
        for (int nt = 0; nt < 4; nt++)
#pragma unroll
            for (int r = 0; r < 4; r++) c[mt][nt][r] = 0.f;

    auto load_chunk = [&](int chunk) {
        const uint32_t dbuf = sbase + (uint32_t)(chunk & 1) * BUFBYTES;
        const int jel = chunk * KC;
#pragma unroll
        for (int p = 0; p < 8; p++) {
            int t = tid + p * 256;
            int op  = t >> 10;
            int row = (t >> 3) & 127;
            int seg = t & 7;
            uint32_t dst = dbuf + (uint32_t)op * OPBYTES + row * RSTRIDE + seg * 16;
            const __nv_bfloat16* src = op
                ? Ag + (size_t)row * NN + jel + seg * 8
                : Vg + (size_t)row * NN + jel + seg * 8;
            CP_ASYNC16(dst, src);
        }
        CP_COMMIT();
    };

    load_chunk(0);

    for (int chunk = 0; chunk < NN / KC; chunk++) {
        if (chunk + 1 < NN / KC) { load_chunk(chunk + 1); CP_WAIT1(); }
        else                     { CP_WAIT0(); }
        __syncthreads();

        const uint32_t aBase = sbase + (uint32_t)(chunk & 1) * BUFBYTES;
        const uint32_t bBase = aBase + OPBYTES;
#pragma unroll
        for (int ks = 0; ks < KC / 16; ks++) {
            const int kb = ks * 32;
            uint32_t a[4][4];
#pragma unroll
            for (int mt = 0; mt < 4; mt++) {
                uint32_t addr = aBase + (m_base + mt * 16 + (lane & 15)) * RSTRIDE
                              + kb + ((lane >> 4) << 4);
                LDMATRIX_X4(a[mt][0], a[mt][1], a[mt][2], a[mt][3], addr);
            }
            uint32_t bf[4][2];
#pragma unroll
            for (int bt = 0; bt < 2; bt++) {
                int row = n_base + bt * 16 + ((lane >> 4) << 3) + (lane & 7);
                uint32_t addr = bBase + row * RSTRIDE + kb + (((lane >> 3) & 1) << 4);
                uint32_t r0, r1, r2, r3;
                LDMATRIX_X4(r0, r1, r2, r3, addr);
                bf[bt * 2 + 0][0] = r0; bf[bt * 2 + 0][1] = r1;
                bf[bt * 2 + 1][0] = r2; bf[bt * 2 + 1][1] = r3;
            }
#pragma unroll
            for (int mt = 0; mt < 4; mt++)
#pragma unroll
                for (int nt = 0; nt < 4; nt++)
                    MMA16816(c[mt][nt], a[mt], bf[nt]);
        }
        __syncthreads();
    }

    // epilogue: gamma * acc * inv_s[n] + x
    const float g = gamma_p[0];
    const int rquad = lane >> 2;
    const int cpair = (lane & 3) * 2;
#pragma unroll
    for (int mt = 0; mt < 4; mt++) {
#pragma unroll
        for (int half = 0; half < 2; half++) {
            int m = m_base + mt * 16 + rquad + half * 8;
            size_t rowoff = ((size_t)(b * CC_ + c0 + m)) * NN + i0;
#pragma unroll
            for (int nt = 0; nt < 4; nt++) {
                int n = n_base + nt * 8 + cpair;
                float2 xv = *(const float2*)&x[rowoff + n];
                float2 r;
                r.x = fmaf(g * invs[n],     c[mt][nt][half * 2 + 0], xv.x);
                r.y = fmaf(g * invs[n + 1], c[mt][nt][half * 2 + 1], xv.y);
                *(float2*)&out[rowoff + n] = r;
            }
        }
    }
}

// ---------------------------------------------------------------------------
extern "C" void kernel_launch(void* const* d_in, const int* in_sizes, int n_in,
                              void* d_out, int out_size)
{
    const float* x     = (const float*)d_in[0];
    const float* wq    = (const float*)d_in[1];
    const float* bq    = (const float*)d_in[2];
    const float* wk    = (const float*)d_in[3];
    const float* bk    = (const float*)d_in[4];
    const float* wv    = (const float*)d_in[5];
    const float* bv    = (const float*)d_in[6];
    const float* gamma = (const float*)d_in[7];
    float* out = (float*)d_out;

    cudaFuncSetAttribute(out_kernel_mma, cudaFuncAttributeMaxDynamicSharedMemorySize, SMEM_D);

    qkv_kernel<<<dim3(64, 4), 256>>>(x, wq, bq, wk, bk, wv, bv);
    transpose_qk<<<dim3(128, 2, 4), dim3(32, 8)>>>();
    energy_softmax_kernel<<<dim3(64, 4), 256>>>();
    out_kernel_mma<<<dim3(32, 2, 4), 256, SMEM_D>>>(x, gamma, out);
}

// round 6
// speedup vs baseline: 4.3143x; 1.2783x over previous
#include <cuda_runtime.h>
#include <cuda_bf16.h>
#include <cstdint>

// Self_Attention: x[B,C,H,W], 1x1-conv projections q,k (D=32), v (C),
// energy = q^T k, softmax over j, out = V @ attn^T, final = gamma*out + x.
// Plain-sm_103 PTX target -> no tcgen05; HMMA (mma.sync) + ldmatrix + cp.async.
// R6: flash-style fusion -- S, exp, rowsum, PV in ONE kernel; no attn matrix.
#define BB 4
#define CC_ 256
#define NN 4096
#define DD 32

// Scratch (device globals; no runtime allocation allowed)
__device__ __nv_bfloat16 g_v16[BB][CC_][NN];   // V bf16, 8 MB
__device__ __nv_bfloat16 g_qk16[BB][64][NN];   // q,k bf16 d-major, 2 MB
__device__ __nv_bfloat16 g_qT[BB][NN][DD];     // q bf16 token-major, 1 MB
__device__ __nv_bfloat16 g_kT[BB][NN][DD];     // k bf16 token-major, 1 MB

__device__ __forceinline__ uint32_t smem_u32(const void* p) {
    uint32_t a;
    asm("{ .reg .u64 t; cvta.to.shared.u64 t, %1; cvt.u32.u64 %0, t; }" : "=r"(a) : "l"(p));
    return a;
}

#define CP_ASYNC16(dst, src) \
    asm volatile("cp.async.cg.shared.global [%0], [%1], 16;" :: "r"(dst), "l"(src))
#define CP_COMMIT()  asm volatile("cp.async.commit_group;")
#define CP_WAIT1()   asm volatile("cp.async.wait_group 1;")
#define CP_WAIT0()   asm volatile("cp.async.wait_group 0;")

#define LDMATRIX_X4(r0, r1, r2, r3, addr)                                          \
    asm volatile("ldmatrix.sync.aligned.m8n8.x4.shared.b16 {%0,%1,%2,%3}, [%4];"   \
        : "=r"(r0), "=r"(r1), "=r"(r2), "=r"(r3) : "r"(addr))

#define MMA16816(c, a, b)                                                          \
    asm volatile("mma.sync.aligned.m16n8k16.row.col.f32.bf16.bf16.f32 "            \
        "{%0,%1,%2,%3}, {%4,%5,%6,%7}, {%8,%9}, {%0,%1,%2,%3};"                    \
        : "+f"((c)[0]), "+f"((c)[1]), "+f"((c)[2]), "+f"((c)[3])                   \
        : "r"((a)[0]), "r"((a)[1]), "r"((a)[2]), "r"((a)[3]),                      \
          "r"((b)[0]), "r"((b)[1]))

// ---------------------------------------------------------------------------
// Kernel A: fused QKV projection. q,k -> bf16 g_qk16 (d-major); v -> g_v16.
// ---------------------------------------------------------------------------
__global__ __launch_bounds__(256) void qkv_kernel(
    const float* __restrict__ x,
    const float* __restrict__ wq, const float* __restrict__ bq,
    const float* __restrict__ wk, const float* __restrict__ bk,
    const float* __restrict__ wv, const float* __restrict__ bv)
{
    __shared__ float xs[128][65];
    const int b  = blockIdx.y;
    const int n0 = blockIdx.x * 64;
    const int tid = threadIdx.x;
    const int tg = tid & 7;
    const int rg = tid >> 3;
    const int t0 = tg * 8;

    float acc[10][8];
#pragma unroll
    for (int r = 0; r < 10; r++)
#pragma unroll
        for (int t = 0; t < 8; t++) acc[r][t] = 0.f;

    const float* wrow[10];
    float bias[10];
#pragma unroll
    for (int rr = 0; rr < 10; rr++) {
        int r = rg * 10 + rr;
        if (r < 32)      { wrow[rr] = wq + r * CC_;        bias[rr] = bq[r]; }
        else if (r < 64) { wrow[rr] = wk + (r - 32) * CC_; bias[rr] = bk[r - 32]; }
        else             { wrow[rr] = wv + (r - 64) * CC_; bias[rr] = bv[r - 64]; }
    }

    for (int half = 0; half < 2; half++) {
        for (int idx = tid; idx < 128 * 64; idx += 256) {
            int cc = idx >> 6, t = idx & 63;
            xs[cc][t] = x[((size_t)(b * CC_ + half * 128 + cc)) * NN + n0 + t];
        }
        __syncthreads();
#pragma unroll 4
        for (int cc = 0; cc < 128; cc++) {
            float xv[8];
#pragma unroll
            for (int t = 0; t < 8; t++) xv[t] = xs[cc][t0 + t];
#pragma unroll
            for (int rr = 0; rr < 10; rr++) {
                float w = wrow[rr][half * 128 + cc];
#pragma unroll
                for (int t = 0; t < 8; t++) acc[rr][t] = fmaf(w, xv[t], acc[rr][t]);
            }
        }
        __syncthreads();
    }

#pragma unroll
    for (int rr = 0; rr < 10; rr++) {
        int r = rg * 10 + rr;
        __nv_bfloat162 pk[4];
#pragma unroll
        for (int t = 0; t < 4; t++)
            pk[t] = __floats2bfloat162_rn(acc[rr][2 * t] + bias[rr],
                                          acc[rr][2 * t + 1] + bias[rr]);
        if (r < 64) *(uint4*)&g_qk16[b][r][n0 + t0]      = *(uint4*)pk;
        else        *(uint4*)&g_v16[b][r - 64][n0 + t0]  = *(uint4*)pk;
    }
}

// ---------------------------------------------------------------------------
// Kernel T: transpose q,k from [d][n] to token-major [n][32] bf16.
// ---------------------------------------------------------------------------
__global__ __launch_bounds__(256) void transpose_qk()
{
    __shared__ __nv_bfloat16 ts[32][33];
    const int b   = blockIdx.z;
    const int sel = blockIdx.y;           // 0 = q, 1 = k
    const int t0  = blockIdx.x * 32;
    const int tx  = threadIdx.x, ty = threadIdx.y;

#pragma unroll
    for (int yy = ty; yy < 32; yy += 8)
        ts[yy][tx] = g_qk16[b][sel * 32 + yy][t0 + tx];
    __syncthreads();

    __nv_bfloat16* outp = sel ? &g_kT[b][0][0] : &g_qT[b][0][0];
#pragma unroll
    for (int yy = ty; yy < 32; yy += 8)
        outp[(size_t)(t0 + yy) * DD + tx] = ts[tx][yy];
}

// ---------------------------------------------------------------------------
// Kernel F (fused flash attention, HMMA):
//   per CTA: i-tile 128 x c-half 128. Loop j in chunks of 64:
//     S[i,j] = q_i.k_j (HMMA, K=32) -> P' = exp(S) packed bf16 in regs
//     (C-frag of S is layout-congruent with A-frag of PV mma)
//     acc[i,c] += P' @ V  (B = V[c][j], k=j contiguous)
//     rowsum += sum_j exp(S)
//   epilogue: out = gamma * acc/rowsum + x.
// 8 warps, each owns 16 i-rows x 128 c. grid (32 i, 2 c, 4 b), 256 thr.
// smem: q 10240 + K 2x5120 + V 2x18432 = 57344 B (dynamic).
// ---------------------------------------------------------------------------
#define QS_OFF   0
#define KC_OFF   10240
#define KC_BUF   5120
#define VC_OFF   20480
#define VC_BUF   18432
#define SMEM_F   57344

__global__ __launch_bounds__(256, 1) void fused_attn_kernel(
    const float* __restrict__ x, const float* __restrict__ gamma_p,
    float* __restrict__ out)
{
    extern __shared__ char smem[];
    const uint32_t sb = smem_u32(smem);
    const int tid  = threadIdx.x;
    const int wid  = tid >> 5;
    const int lane = tid & 31;
    const int b  = blockIdx.z;
    const int c0 = blockIdx.y * 128;
    const int i0 = blockIdx.x * 128;
    const int mq = wid;                 // warp's 16 i-rows: mq*16..+15

    // ---- chunk loaders ----
    auto load_chunk = [&](int chunk) {
        const int j0 = chunk * 64;
        // K: 64 rows x 32 bf16 (4 x 16B segs) = 256 transfers
        {
            int row = tid >> 2, seg = tid & 3;
            CP_ASYNC16(sb + KC_OFF + (chunk & 1) * KC_BUF + row * 80 + seg * 16,
                       &g_kT[b][j0 + row][seg * 8]);
        }
        // V: 128 rows x 64 bf16 (8 x 16B segs) = 1024 transfers, 4/thread
#pragma unroll
        for (int p = 0; p < 4; p++) {
            int idx = tid + p * 256;
            int row = idx >> 3, seg = idx & 7;
            CP_ASYNC16(sb + VC_OFF + (chunk & 1) * VC_BUF + row * 144 + seg * 16,
                       &g_v16[b][c0 + row][j0 + seg * 8]);
        }
        CP_COMMIT();
    };

    // q tile (once): 128 rows x 32 bf16, 512 transfers, 2/thread — group 0
    {
#pragma unroll
        for (int p = 0; p < 2; p++) {
            int idx = tid + p * 256;
            int row = idx >> 2, seg = idx & 3;
            CP_ASYNC16(sb + QS_OFF + row * 80 + seg * 16, &g_qT[b][i0 + row][seg * 8]);
        }
    }
    load_chunk(0);   // commits q + chunk0 together as group 0

    float acc[16][4];
#pragma unroll
    for (int nt = 0; nt < 16; nt++)
#pragma unroll
        for (int r = 0; r < 4; r++) acc[nt][r] = 0.f;

    uint32_t qf[2][4];
    float sum0 = 0.f, sum1 = 0.f;

    for (int chunk = 0; chunk < NN / 64; chunk++) {
        if (chunk + 1 < NN / 64) { load_chunk(chunk + 1); CP_WAIT1(); }
        else                     { CP_WAIT0(); }
        __syncthreads();

        if (chunk == 0) {
            // load q A-frags once (rows mq*16..+15, k = 0..31)
#pragma unroll
            for (int ks = 0; ks < 2; ks++) {
                uint32_t addr = sb + QS_OFF + (mq * 16 + (lane & 15)) * 80
                              + ks * 32 + ((lane >> 4) << 4);
                LDMATRIX_X4(qf[ks][0], qf[ks][1], qf[ks][2], qf[ks][3], addr);
            }
        }

        // ---- S = q.k over this 64-j chunk ----
        const uint32_t kbuf = sb + KC_OFF + (chunk & 1) * KC_BUF;
        float cc[8][4];
#pragma unroll
        for (int nt = 0; nt < 8; nt++)
#pragma unroll
            for (int r = 0; r < 4; r++) cc[nt][r] = 0.f;

#pragma unroll
        for (int ks = 0; ks < 2; ks++) {
            uint32_t kb[8][2];
#pragma unroll
            for (int bt = 0; bt < 4; bt++) {
                int row = bt * 16 + ((lane >> 4) << 3) + (lane & 7);
                uint32_t addr = kbuf + row * 80 + ks * 32 + (((lane >> 3) & 1) << 4);
                uint32_t r0, r1, r2, r3;
                LDMATRIX_X4(r0, r1, r2, r3, addr);
                kb[bt * 2 + 0][0] = r0; kb[bt * 2 + 0][1] = r1;
                kb[bt * 2 + 1][0] = r2; kb[bt * 2 + 1][1] = r3;
            }
#pragma unroll
            for (int nt = 0; nt < 8; nt++) MMA16816(cc[nt], qf[ks], kb[nt]);
        }

        // ---- exp + rowsum + repack C-frags -> A-frags of PV mma ----
        uint32_t aP[4][4];
#pragma unroll
        for (int nt = 0; nt < 8; nt++) {
            float e0 = __expf(cc[nt][0]);
            float e1 = __expf(cc[nt][1]);
            float e2 = __expf(cc[nt][2]);
            float e3 = __expf(cc[nt][3]);
            sum0 += e0 + e1;
            sum1 += e2 + e3;
            __nv_bfloat162 pA = __floats2bfloat162_rn(e0, e1);
            __nv_bfloat162 pB = __floats2bfloat162_rn(e2, e3);
            int kk = nt >> 1;
            if ((nt & 1) == 0) { aP[kk][0] = *(uint32_t*)&pA; aP[kk][1] = *(uint32_t*)&pB; }
            else               { aP[kk][2] = *(uint32_t*)&pA; aP[kk][3] = *(uint32_t*)&pB; }
        }

        // ---- acc += P' @ V ----
        const uint32_t vbuf = sb + VC_OFF + (chunk & 1) * VC_BUF;
#pragma unroll
        for (int kk = 0; kk < 4; kk++) {
            uint32_t vb[16][2];
#pragma unroll
            for (int bt = 0; bt < 8; bt++) {
                int row = bt * 16 + ((lane >> 4) << 3) + (lane & 7);
                uint32_t addr = vbuf + row * 144 + kk * 32 + (((lane >> 3) & 1) << 4);
                uint32_t r0, r1, r2, r3;
                LDMATRIX_X4(r0, r1, r2, r3, addr);
                vb[bt * 2 + 0][0] = r0; vb[bt * 2 + 0][1] = r1;
                vb[bt * 2 + 1][0] = r2; vb[bt * 2 + 1][1] = r3;
            }
#pragma unroll
            for (int nt = 0; nt < 16; nt++) MMA16816(acc[nt], aP[kk], vb[nt]);
        }
        __syncthreads();
    }

    // ---- normalize: rows r=mq*16+(lane>>2) and r+8 ----
    sum0 += __shfl_xor_sync(0xffffffffu, sum0, 1);
    sum0 += __shfl_xor_sync(0xffffffffu, sum0, 2);
    sum1 += __shfl_xor_sync(0xffffffffu, sum1, 1);
    sum1 += __shfl_xor_sync(0xffffffffu, sum1, 2);
    const float inv0 = 1.0f / sum0;
    const float inv1 = 1.0f / sum1;
#pragma unroll
    for (int nt = 0; nt < 16; nt++) {
        acc[nt][0] *= inv0; acc[nt][1] *= inv0;
        acc[nt][2] *= inv1; acc[nt][3] *= inv1;
    }

    // ---- epilogue: out[c, i] = gamma*acc + x ----
    const float gam = gamma_p[0];
    const int g2 = lane >> 2;          // i row within warp tile
    const int tg = lane & 3;
    const int irow = i0 + mq * 16 + g2;
#pragma unroll
    for (int nt = 0; nt < 16; nt++) {
        int c = c0 + nt * 8 + tg * 2;
        size_t o00 = ((size_t)(b * CC_ + c)) * NN + irow;      // (c,   i)
        size_t o10 = o00 + NN;                                  // (c+1, i)
        out[o00]     = fmaf(gam, acc[nt][0], x[o00]);
        out[o10]     = fmaf(gam, acc[nt][1], x[o10]);
        out[o00 + 8] = fmaf(gam, acc[nt][2], x[o00 + 8]);       // (c,   i+8)
        out[o10 + 8] = fmaf(gam, acc[nt][3], x[o10 + 8]);       // (c+1, i+8)
    }
}

// ---------------------------------------------------------------------------
extern "C" void kernel_launch(void* const* d_in, const int* in_sizes, int n_in,
                              void* d_out, int out_size)
{
    const float* x     = (const float*)d_in[0];
    const float* wq    = (const float*)d_in[1];
    const float* bq    = (const float*)d_in[2];
    const float* wk    = (const float*)d_in[3];
    const float* bk    = (const float*)d_in[4];
    const float* wv    = (const float*)d_in[5];
    const float* bv    = (const float*)d_in[6];
    const float* gamma = (const float*)d_in[7];
    float* out = (float*)d_out;

    cudaFuncSetAttribute(fused_attn_kernel,
                         cudaFuncAttributeMaxDynamicSharedMemorySize, SMEM_F);

    qkv_kernel<<<dim3(64, 4), 256>>>(x, wq, bq, wk, bk, wv, bv);
    transpose_qk<<<dim3(128, 2, 4), dim3(32, 8)>>>();
    fused_attn_kernel<<<dim3(32, 2, 4), 256, SMEM_F>>>(x, gamma, out);
}

// round 7
// speedup vs baseline: 7.2951x; 1.6909x over previous
#include <cuda_runtime.h>
#include <cuda_bf16.h>
#include <cstdint>

// Self_Attention: x[B,C,H,W], 1x1-conv projections q,k (D=32), v (C),
// energy = q^T k, softmax over j, out = V @ attn^T, final = gamma*out + x.
// Plain-sm_103 PTX target -> no tcgen05; HMMA (mma.sync) + ldmatrix + cp.async.
// R7: QKV projection moved to HMMA; q/k written token-major directly from
// C-fragments (transpose kernel eliminated).
#define BB 4
#define CC_ 256
#define NN 4096
#define DD 32

// Scratch (device globals; no runtime allocation allowed)
__device__ __nv_bfloat16 g_v16[BB][CC_][NN];   // V bf16, 8 MB
__device__ __nv_bfloat16 g_qT[BB][NN][DD];     // q bf16 token-major, 1 MB
__device__ __nv_bfloat16 g_kT[BB][NN][DD];     // k bf16 token-major, 1 MB
__device__ __nv_bfloat16 g_w16[320][CC_];      // W bf16 (q,k,v stacked), 160 KB
__device__ float g_biasf[320];                 // biases (q,k,v stacked)

__device__ __forceinline__ uint32_t smem_u32(const void* p) {
    uint32_t a;
    asm("{ .reg .u64 t; cvta.to.shared.u64 t, %1; cvt.u32.u64 %0, t; }" : "=r"(a) : "l"(p));
    return a;
}

#define CP_ASYNC16(dst, src) \
    asm volatile("cp.async.cg.shared.global [%0], [%1], 16;" :: "r"(dst), "l"(src))
#define CP_COMMIT()  asm volatile("cp.async.commit_group;")
#define CP_WAIT1()   asm volatile("cp.async.wait_group 1;")
#define CP_WAIT0()   asm volatile("cp.async.wait_group 0;")

#define LDMATRIX_X4(r0, r1, r2, r3, addr)                                          \
    asm volatile("ldmatrix.sync.aligned.m8n8.x4.shared.b16 {%0,%1,%2,%3}, [%4];"   \
        : "=r"(r0), "=r"(r1), "=r"(r2), "=r"(r3) : "r"(addr))

#define MMA16816(c, a, b)                                                          \
    asm volatile("mma.sync.aligned.m16n8k16.row.col.f32.bf16.bf16.f32 "            \
        "{%0,%1,%2,%3}, {%4,%5,%6,%7}, {%8,%9}, {%0,%1,%2,%3};"                    \
        : "+f"((c)[0]), "+f"((c)[1]), "+f"((c)[2]), "+f"((c)[3])                   \
        : "r"((a)[0]), "r"((a)[1]), "r"((a)[2]), "r"((a)[3]),                      \
          "r"((b)[0]), "r"((b)[1]))

// ---------------------------------------------------------------------------
// Kernel W: convert weights to bf16 (rows 0-31 q, 32-63 k, 64-319 v) + biases.
// ---------------------------------------------------------------------------
__global__ __launch_bounds__(256) void wconv_kernel(
    const float* __restrict__ wq, const float* __restrict__ bq,
    const float* __restrict__ wk, const float* __restrict__ bk,
    const float* __restrict__ wv, const float* __restrict__ bv)
{
    const int row = blockIdx.x;
    const int t = threadIdx.x;
    const float* src = row < 32 ? wq + row * CC_
                     : row < 64 ? wk + (row - 32) * CC_
                                : wv + (row - 64) * CC_;
    g_w16[row][t] = __float2bfloat16(src[t]);
    if (t == 0)
        g_biasf[row] = row < 32 ? bq[row] : row < 64 ? bk[row - 32] : bv[row - 64];
}

// ---------------------------------------------------------------------------
// Kernel A (HMMA QKV): per CTA 128 tokens, all 320 output rows, K=256 in 4
// chunks of 64. W fully smem-resident (cp.async once). x fp32 loaded per
// chunk (register prefetch), converted+transposed to bf16 smem [token][c].
//   qk: C[token][r]   = x-tile @ W^T  -> g_qT/g_kT directly (token-major)
//   v : C[vrow][token] = W @ x-tile^T -> g_v16 directly
// 8 warps: QK -> warp w owns tokens w*16..+15 (8 r-ntiles).
//          V  -> warp w: mw=w>>1 owns vrows mw*64..+63, nw=w&1 tokens nw*64.
// grid (32, 4), 256 threads, 188672 B dyn smem.
// ---------------------------------------------------------------------------
#define WROW    528                       // 256 bf16 + 16 pad
#define WS_OFF  0                         // 320 x 528 = 168960
#define XROW    144                       // 64 bf16 + 16 pad
#define XS_OFF  168960                    // 128 x 144 = 18432
#define BI_OFF  (168960 + 18432)          // 320 floats
#define SMEM_Q  (168960 + 18432 + 1280)   // 188672

__global__ __launch_bounds__(256, 1) void qkv_hmma_kernel(
    const float* __restrict__ x)
{
    extern __shared__ char smq[];
    const uint32_t sb = smem_u32(smq);
    const int tid  = threadIdx.x;
    const int wid  = tid >> 5;
    const int lane = tid & 31;
    const int b  = blockIdx.y;
    const int n0 = blockIdx.x * 128;

    // W -> smem (once): 320 rows x 32 16B segs = 10240 transfers, 40/thread
#pragma unroll
    for (int p = 0; p < 40; p++) {
        int idx = tid + p * 256;
        int row = idx >> 5, seg = idx & 31;
        CP_ASYNC16(sb + WS_OFF + row * WROW + seg * 16, &g_w16[row][seg * 8]);
    }
    if (tid < 80) CP_ASYNC16(sb + BI_OFF + tid * 16, &g_biasf[tid * 4]);
    CP_COMMIT();

    float accQ[8][4];
    float accV[4][8][4];
#pragma unroll
    for (int nt = 0; nt < 8; nt++)
#pragma unroll
        for (int r = 0; r < 4; r++) accQ[nt][r] = 0.f;
#pragma unroll
    for (int mt = 0; mt < 4; mt++)
#pragma unroll
        for (int nt = 0; nt < 8; nt++)
#pragma unroll
            for (int r = 0; r < 4; r++) accV[mt][nt][r] = 0.f;

    const int mw = wid >> 1;            // V row group (64 rows)
    const int nw = wid & 1;             // V token half (64 tokens)
    const int ntok = tid & 127;         // this thread's token for x staging
    const int cgrp = (tid >> 7) * 32;   // c base within chunk (0 or 32)

    // prefetch x chunk 0: 32 fp32 per thread (c = ck*64+cgrp+q, token ntok)
    float xr[32];
    {
        const float* xp = x + ((size_t)(b * CC_ + cgrp)) * NN + n0 + ntok;
#pragma unroll
        for (int q = 0; q < 32; q++) xr[q] = xp[(size_t)q * NN];
    }

    for (int ck = 0; ck < 4; ck++) {
        __syncthreads();   // prev chunk's compute done reading xs
        // convert + transpose into xs[token][c_local]
#pragma unroll
        for (int q = 0; q < 16; q++) {
            __nv_bfloat162 pk = __floats2bfloat162_rn(xr[2 * q], xr[2 * q + 1]);
            *(uint32_t*)(smq + XS_OFF + ntok * XROW + (cgrp + 2 * q) * 2) =
                *(uint32_t*)&pk;
        }
        if (ck == 0) CP_WAIT0();   // W + bias resident
        __syncthreads();

        // prefetch next chunk while computing this one
        if (ck < 3) {
            const float* xp = x + ((size_t)(b * CC_ + (ck + 1) * 64 + cgrp)) * NN
                            + n0 + ntok;
#pragma unroll
            for (int q = 0; q < 32; q++) xr[q] = xp[(size_t)q * NN];
        }

        const uint32_t wbase = sb + WS_OFF + ck * 128;  // byte offset of chunk in W rows
#pragma unroll
        for (int ks = 0; ks < 4; ks++) {
            const int kb = ks * 32;
            // ---- QK: A = x rows (warp's 16 tokens) ----
            uint32_t ax[4];
            {
                uint32_t addr = sb + XS_OFF + (wid * 16 + (lane & 15)) * XROW
                              + kb + ((lane >> 4) << 4);
                LDMATRIX_X4(ax[0], ax[1], ax[2], ax[3], addr);
            }
            // B = W rows 0..63 (q,k)
            uint32_t bw[8][2];
#pragma unroll
            for (int bt = 0; bt < 4; bt++) {
                int row = bt * 16 + ((lane >> 4) << 3) + (lane & 7);
                uint32_t addr = wbase + row * WROW + kb + (((lane >> 3) & 1) << 4);
                uint32_t r0, r1, r2, r3;
                LDMATRIX_X4(r0, r1, r2, r3, addr);
                bw[bt * 2 + 0][0] = r0; bw[bt * 2 + 0][1] = r1;
                bw[bt * 2 + 1][0] = r2; bw[bt * 2 + 1][1] = r3;
            }
#pragma unroll
            for (int nt = 0; nt < 8; nt++) MMA16816(accQ[nt], ax, bw[nt]);

            // ---- V: A = W rows 64 + mw*64 .. (+64), B = x rows (nw tokens) ----
            uint32_t aw[4][4];
#pragma unroll
            for (int mt = 0; mt < 4; mt++) {
                uint32_t addr = wbase + (64 + mw * 64 + mt * 16 + (lane & 15)) * WROW
                              + kb + ((lane >> 4) << 4);
                LDMATRIX_X4(aw[mt][0], aw[mt][1], aw[mt][2], aw[mt][3], addr);
            }
            uint32_t bx[8][2];
#pragma unroll
            for (int bt = 0; bt < 4; bt++) {
                int row = nw * 64 + bt * 16 + ((lane >> 4) << 3) + (lane & 7);
                uint32_t addr = sb + XS_OFF + row * XROW + kb
                              + (((lane >> 3) & 1) << 4);
                uint32_t r0, r1, r2, r3;
                LDMATRIX_X4(r0, r1, r2, r3, addr);
                bx[bt * 2 + 0][0] = r0; bx[bt * 2 + 0][1] = r1;
                bx[bt * 2 + 1][0] = r2; bx[bt * 2 + 1][1] = r3;
            }
#pragma unroll
            for (int mt = 0; mt < 4; mt++)
#pragma unroll
                for (int nt = 0; nt < 8; nt++)
                    MMA16816(accV[mt][nt], aw[mt], bx[nt]);
        }
    }

    const float* biasS = (const float*)(smq + BI_OFF);

    // ---- QK epilogue: rows = tokens, cols = r (0..63) ----
    {
        int rq = n0 + wid * 16 + (lane >> 2);
#pragma unroll
        for (int nt = 0; nt < 8; nt++) {
            int r = nt * 8 + (lane & 3) * 2;
            float b0 = biasS[r], b1 = biasS[r + 1];
            __nv_bfloat162 pA = __floats2bfloat162_rn(accQ[nt][0] + b0,
                                                      accQ[nt][1] + b1);
            __nv_bfloat162 pB = __floats2bfloat162_rn(accQ[nt][2] + b0,
                                                      accQ[nt][3] + b1);
            if (nt < 4) {
                *(uint32_t*)&g_qT[b][rq][r]     = *(uint32_t*)&pA;
                *(uint32_t*)&g_qT[b][rq + 8][r] = *(uint32_t*)&pB;
            } else {
                *(uint32_t*)&g_kT[b][rq][r - 32]     = *(uint32_t*)&pA;
                *(uint32_t*)&g_kT[b][rq + 8][r - 32] = *(uint32_t*)&pB;
            }
        }
    }

    // ---- V epilogue: rows = v-channels, cols = tokens ----
#pragma unroll
    for (int mt = 0; mt < 4; mt++) {
        int vr = mw * 64 + mt * 16 + (lane >> 2);
        float b0 = biasS[64 + vr], b1 = biasS[64 + vr + 8];
#pragma unroll
        for (int nt = 0; nt < 8; nt++) {
            int col = n0 + nw * 64 + nt * 8 + (lane & 3) * 2;
            __nv_bfloat162 pA = __floats2bfloat162_rn(accV[mt][nt][0] + b0,
                                                      accV[mt][nt][1] + b0);
            __nv_bfloat162 pB = __floats2bfloat162_rn(accV[mt][nt][2] + b1,
                                                      accV[mt][nt][3] + b1);
            *(uint32_t*)&g_v16[b][vr][col]     = *(uint32_t*)&pA;
            *(uint32_t*)&g_v16[b][vr + 8][col] = *(uint32_t*)&pB;
        }
    }
}

// ---------------------------------------------------------------------------
// Kernel F (fused flash attention, HMMA): unchanged from R6.
//   per CTA: i-tile 128 x c-half 128; loop j chunks of 64:
//   S = q.k -> P' = exp(S) (C-frag == A-frag layout), acc += P'@V, rowsum.
//   epilogue: out = gamma * acc/rowsum + x.
// ---------------------------------------------------------------------------
#define QS_OFF   0
#define KC_OFF   10240
#define KC_BUF   5120
#define VC_OFF   20480
#define VC_BUF   18432
#define SMEM_F   57344

__global__ __launch_bounds__(256, 1) void fused_attn_kernel(
    const float* __restrict__ x, const float* __restrict__ gamma_p,
    float* __restrict__ out)
{
    extern __shared__ char smem[];
    const uint32_t sb = smem_u32(smem);
    const int tid  = threadIdx.x;
    const int wid  = tid >> 5;
    const int lane = tid & 31;
    const int b  = blockIdx.z;
    const int c0 = blockIdx.y * 128;
    const int i0 = blockIdx.x * 128;
    const int mq = wid;

    auto load_chunk = [&](int chunk) {
        const int j0 = chunk * 64;
        {
            int row = tid >> 2, seg = tid & 3;
            CP_ASYNC16(sb + KC_OFF + (chunk & 1) * KC_BUF + row * 80 + seg * 16,
                       &g_kT[b][j0 + row][seg * 8]);
        }
#pragma unroll
        for (int p = 0; p < 4; p++) {
            int idx = tid + p * 256;
            int row = idx >> 3, seg = idx & 7;
            CP_ASYNC16(sb + VC_OFF + (chunk & 1) * VC_BUF + row * 144 + seg * 16,
                       &g_v16[b][c0 + row][j0 + seg * 8]);
        }
        CP_COMMIT();
    };

    {
#pragma unroll
        for (int p = 0; p < 2; p++) {
            int idx = tid + p * 256;
            int row = idx >> 2, seg = idx & 3;
            CP_ASYNC16(sb + QS_OFF + row * 80 + seg * 16, &g_qT[b][i0 + row][seg * 8]);
        }
    }
    load_chunk(0);

    float acc[16][4];
#pragma unroll
    for (int nt = 0; nt < 16; nt++)
#pragma unroll
        for (int r = 0; r < 4; r++) acc[nt][r] = 0.f;

    uint32_t qf[2][4];
    float sum0 = 0.f, sum1 = 0.f;

    for (int chunk = 0; chunk < NN / 64; chunk++) {
        if (chunk + 1 < NN / 64) { load_chunk(chunk + 1); CP_WAIT1(); }
        else                     { CP_WAIT0(); }
        __syncthreads();

        if (chunk == 0) {
#pragma unroll
            for (int ks = 0; ks < 2; ks++) {
                uint32_t addr = sb + QS_OFF + (mq * 16 + (lane & 15)) * 80
                              + ks * 32 + ((lane >> 4) << 4);
                LDMATRIX_X4(qf[ks][0], qf[ks][1], qf[ks][2], qf[ks][3], addr);
            }
        }

        const uint32_t kbuf = sb + KC_OFF + (chunk & 1) * KC_BUF;
        float cc[8][4];
#pragma unroll
        for (int nt = 0; nt < 8; nt++)
#pragma unroll
            for (int r = 0; r < 4; r++) cc[nt][r] = 0.f;

#pragma unroll
        for (int ks = 0; ks < 2; ks++) {
            uint32_t kb[8][2];
#pragma unroll
            for (int bt = 0; bt < 4; bt++) {
                int row = bt * 16 + ((lane >> 4) << 3) + (lane & 7);
                uint32_t addr = kbuf + row * 80 + ks * 32 + (((lane >> 3) & 1) << 4);
                uint32_t r0, r1, r2, r3;
                LDMATRIX_X4(r0, r1, r2, r3, addr);
                kb[bt * 2 + 0][0] = r0; kb[bt * 2 + 0][1] = r1;
                kb[bt * 2 + 1][0] = r2; kb[bt * 2 + 1][1] = r3;
            }
#pragma unroll
            for (int nt = 0; nt < 8; nt++) MMA16816(cc[nt], qf[ks], kb[nt]);
        }

        uint32_t aP[4][4];
#pragma unroll
        for (int nt = 0; nt < 8; nt++) {
            float e0 = __expf(cc[nt][0]);
            float e1 = __expf(cc[nt][1]);
            float e2 = __expf(cc[nt][2]);
            float e3 = __expf(cc[nt][3]);
            sum0 += e0 + e1;
            sum1 += e2 + e3;
            __nv_bfloat162 pA = __floats2bfloat162_rn(e0, e1);
            __nv_bfloat162 pB = __floats2bfloat162_rn(e2, e3);
            int kk = nt >> 1;
            if ((nt & 1) == 0) { aP[kk][0] = *(uint32_t*)&pA; aP[kk][1] = *(uint32_t*)&pB; }
            else               { aP[kk][2] = *(uint32_t*)&pA; aP[kk][3] = *(uint32_t*)&pB; }
        }

        const uint32_t vbuf = sb + VC_OFF + (chunk & 1) * VC_BUF;
#pragma unroll
        for (int kk = 0; kk < 4; kk++) {
            uint32_t vb[16][2];
#pragma unroll
            for (int bt = 0; bt < 8; bt++) {
                int row = bt * 16 + ((lane >> 4) << 3) + (lane & 7);
                uint32_t addr = vbuf + row * 144 + kk * 32 + (((lane >> 3) & 1) << 4);
                uint32_t r0, r1, r2, r3;
                LDMATRIX_X4(r0, r1, r2, r3, addr);
                vb[bt * 2 + 0][0] = r0; vb[bt * 2 + 0][1] = r1;
                vb[bt * 2 + 1][0] = r2; vb[bt * 2 + 1][1] = r3;
            }
#pragma unroll
            for (int nt = 0; nt < 16; nt++) MMA16816(acc[nt], aP[kk], vb[nt]);
        }
        __syncthreads();
    }

    sum0 += __shfl_xor_sync(0xffffffffu, sum0, 1);
    sum0 += __shfl_xor_sync(0xffffffffu, sum0, 2);
    sum1 += __shfl_xor_sync(0xffffffffu, sum1, 1);
    sum1 += __shfl_xor_sync(0xffffffffu, sum1, 2);
    const float inv0 = 1.0f / sum0;
    const float inv1 = 1.0f / sum1;
#pragma unroll
    for (int nt = 0; nt < 16; nt++) {
        acc[nt][0] *= inv0; acc[nt][1] *= inv0;
        acc[nt][2] *= inv1; acc[nt][3] *= inv1;
    }

    const float gam = gamma_p[0];
    const int g2 = lane >> 2;
    const int tg = lane & 3;
    const int irow = i0 + mq * 16 + g2;
#pragma unroll
    for (int nt = 0; nt < 16; nt++) {
        int c = c0 + nt * 8 + tg * 2;
        size_t o00 = ((size_t)(b * CC_ + c)) * NN + irow;
        size_t o10 = o00 + NN;
        out[o00]     = fmaf(gam, acc[nt][0], x[o00]);
        out[o10]     = fmaf(gam, acc[nt][1], x[o10]);
        out[o00 + 8] = fmaf(gam, acc[nt][2], x[o00 + 8]);
        out[o10 + 8] = fmaf(gam, acc[nt][3], x[o10 + 8]);
    }
}

// ---------------------------------------------------------------------------
extern "C" void kernel_launch(void* const* d_in, const int* in_sizes, int n_in,
                              void* d_out, int out_size)
{
    const float* x     = (const float*)d_in[0];
    const float* wq    = (const float*)d_in[1];
    const float* bq    = (const float*)d_in[2];
    const float* wk    = (const float*)d_in[3];
    const float* bk    = (const float*)d_in[4];
    const float* wv    = (const float*)d_in[5];
    const float* bv    = (const float*)d_in[6];
    const float* gamma = (const float*)d_in[7];
    float* out = (float*)d_out;

    cudaFuncSetAttribute(qkv_hmma_kernel,
                         cudaFuncAttributeMaxDynamicSharedMemorySize, SMEM_Q);
    cudaFuncSetAttribute(fused_attn_kernel,
                         cudaFuncAttributeMaxDynamicSharedMemorySize, SMEM_F);

    wconv_kernel<<<dim3(320), 256>>>(wq, bq, wk, bk, wv, bv);
    qkv_hmma_kernel<<<dim3(32, 4), 256, SMEM_Q>>>(x);
    fused_attn_kernel<<<dim3(32, 2, 4), 256, SMEM_F>>>(x, gamma, out);
}

// round 8
// speedup vs baseline: 7.4187x; 1.0169x over previous
#include <cuda_runtime.h>
#include <cuda_bf16.h>
#include <cstdint>

// Self_Attention: x[B,C,H,W], 1x1-conv projections q,k (D=32), v (C),
// energy = q^T k, softmax over j, out = V @ attn^T, final = gamma*out + x.
// Plain-sm_103 PTX target -> no tcgen05; HMMA (mma.sync) + ldmatrix + cp.async.
// R8: fused_attn at 2 CTAs/SM (launch_bounds(256,2)) with liveness-trimmed
// inner loops so the 128-reg cap does not spill.
#define BB 4
#define CC_ 256
#define NN 4096
#define DD 32

// Scratch (device globals; no runtime allocation allowed)
__device__ __nv_bfloat16 g_v16[BB][CC_][NN];   // V bf16, 8 MB
__device__ __nv_bfloat16 g_qT[BB][NN][DD];     // q bf16 token-major, 1 MB
__device__ __nv_bfloat16 g_kT[BB][NN][DD];     // k bf16 token-major, 1 MB
__device__ __nv_bfloat16 g_w16[320][CC_];      // W bf16 (q,k,v stacked), 160 KB
__device__ float g_biasf[320];                 // biases (q,k,v stacked)

__device__ __forceinline__ uint32_t smem_u32(const void* p) {
    uint32_t a;
    asm("{ .reg .u64 t; cvta.to.shared.u64 t, %1; cvt.u32.u64 %0, t; }" : "=r"(a) : "l"(p));
    return a;
}

#define CP_ASYNC16(dst, src) \
    asm volatile("cp.async.cg.shared.global [%0], [%1], 16;" :: "r"(dst), "l"(src))
#define CP_COMMIT()  asm volatile("cp.async.commit_group;")
#define CP_WAIT1()   asm volatile("cp.async.wait_group 1;")
#define CP_WAIT0()   asm volatile("cp.async.wait_group 0;")

#define LDMATRIX_X4(r0, r1, r2, r3, addr)                                          \
    asm volatile("ldmatrix.sync.aligned.m8n8.x4.shared.b16 {%0,%1,%2,%3}, [%4];"   \
        : "=r"(r0), "=r"(r1), "=r"(r2), "=r"(r3) : "r"(addr))

#define MMA16816(c, a, b)                                                          \
    asm volatile("mma.sync.aligned.m16n8k16.row.col.f32.bf16.bf16.f32 "            \
        "{%0,%1,%2,%3}, {%4,%5,%6,%7}, {%8,%9}, {%0,%1,%2,%3};"                    \
        : "+f"((c)[0]), "+f"((c)[1]), "+f"((c)[2]), "+f"((c)[3])                   \
        : "r"((a)[0]), "r"((a)[1]), "r"((a)[2]), "r"((a)[3]),                      \
          "r"((b)[0]), "r"((b)[1]))

// ---------------------------------------------------------------------------
// Kernel W: convert weights to bf16 (rows 0-31 q, 32-63 k, 64-319 v) + biases.
// ---------------------------------------------------------------------------
__global__ __launch_bounds__(256) void wconv_kernel(
    const float* __restrict__ wq, const float* __restrict__ bq,
    const float* __restrict__ wk, const float* __restrict__ bk,
    const float* __restrict__ wv, const float* __restrict__ bv)
{
    const int row = blockIdx.x;
    const int t = threadIdx.x;
    const float* src = row < 32 ? wq + row * CC_
                     : row < 64 ? wk + (row - 32) * CC_
                                : wv + (row - 64) * CC_;
    g_w16[row][t] = __float2bfloat16(src[t]);
    if (t == 0)
        g_biasf[row] = row < 32 ? bq[row] : row < 64 ? bk[row - 32] : bv[row - 64];
}

// ---------------------------------------------------------------------------
// Kernel A (HMMA QKV): unchanged from R7.
// ---------------------------------------------------------------------------
#define WROW    528
#define WS_OFF  0
#define XROW    144
#define XS_OFF  168960
#define BI_OFF  (168960 + 18432)
#define SMEM_Q  (168960 + 18432 + 1280)

__global__ __launch_bounds__(256, 1) void qkv_hmma_kernel(
    const float* __restrict__ x)
{
    extern __shared__ char smq[];
    const uint32_t sb = smem_u32(smq);
    const int tid  = threadIdx.x;
    const int wid  = tid >> 5;
    const int lane = tid & 31;
    const int b  = blockIdx.y;
    const int n0 = blockIdx.x * 128;

#pragma unroll
    for (int p = 0; p < 40; p++) {
        int idx = tid + p * 256;
        int row = idx >> 5, seg = idx & 31;
        CP_ASYNC16(sb + WS_OFF + row * WROW + seg * 16, &g_w16[row][seg * 8]);
    }
    if (tid < 80) CP_ASYNC16(sb + BI_OFF + tid * 16, &g_biasf[tid * 4]);
    CP_COMMIT();

    float accQ[8][4];
    float accV[4][8][4];
#pragma unroll
    for (int nt = 0; nt < 8; nt++)
#pragma unroll
        for (int r = 0; r < 4; r++) accQ[nt][r] = 0.f;
#pragma unroll
    for (int mt = 0; mt < 4; mt++)
#pragma unroll
        for (int nt = 0; nt < 8; nt++)
#pragma unroll
            for (int r = 0; r < 4; r++) accV[mt][nt][r] = 0.f;

    const int mw = wid >> 1;
    const int nw = wid & 1;
    const int ntok = tid & 127;
    const int cgrp = (tid >> 7) * 32;

    float xr[32];
    {
        const float* xp = x + ((size_t)(b * CC_ + cgrp)) * NN + n0 + ntok;
#pragma unroll
        for (int q = 0; q < 32; q++) xr[q] = xp[(size_t)q * NN];
    }

    for (int ck = 0; ck < 4; ck++) {
        __syncthreads();
#pragma unroll
        for (int q = 0; q < 16; q++) {
            __nv_bfloat162 pk = __floats2bfloat162_rn(xr[2 * q], xr[2 * q + 1]);
            *(uint32_t*)(smq + XS_OFF + ntok * XROW + (cgrp + 2 * q) * 2) =
                *(uint32_t*)&pk;
        }
        if (ck == 0) CP_WAIT0();
        __syncthreads();

        if (ck < 3) {
            const float* xp = x + ((size_t)(b * CC_ + (ck + 1) * 64 + cgrp)) * NN
                            + n0 + ntok;
#pragma unroll
            for (int q = 0; q < 32; q++) xr[q] = xp[(size_t)q * NN];
        }

        const uint32_t wbase = sb + WS_OFF + ck * 128;
#pragma unroll
        for (int ks = 0; ks < 4; ks++) {
            const int kb = ks * 32;
            uint32_t ax[4];
            {
                uint32_t addr = sb + XS_OFF + (wid * 16 + (lane & 15)) * XROW
                              + kb + ((lane >> 4) << 4);
                LDMATRIX_X4(ax[0], ax[1], ax[2], ax[3], addr);
            }
            uint32_t bw[8][2];
#pragma unroll
            for (int bt = 0; bt < 4; bt++) {
                int row = bt * 16 + ((lane >> 4) << 3) + (lane & 7);
                uint32_t addr = wbase + row * WROW + kb + (((lane >> 3) & 1) << 4);
                uint32_t r0, r1, r2, r3;
                LDMATRIX_X4(r0, r1, r2, r3, addr);
                bw[bt * 2 + 0][0] = r0; bw[bt * 2 + 0][1] = r1;
                bw[bt * 2 + 1][0] = r2; bw[bt * 2 + 1][1] = r3;
            }
#pragma unroll
            for (int nt = 0; nt < 8; nt++) MMA16816(accQ[nt], ax, bw[nt]);

            uint32_t aw[4][4];
#pragma unroll
            for (int mt = 0; mt < 4; mt++) {
                uint32_t addr = wbase + (64 + mw * 64 + mt * 16 + (lane & 15)) * WROW
                              + kb + ((lane >> 4) << 4);
                LDMATRIX_X4(aw[mt][0], aw[mt][1], aw[mt][2], aw[mt][3], addr);
            }
            uint32_t bx[8][2];
#pragma unroll
            for (int bt = 0; bt < 4; bt++) {
                int row = nw * 64 + bt * 16 + ((lane >> 4) << 3) + (lane & 7);
                uint32_t addr = sb + XS_OFF + row * XROW + kb
                              + (((lane >> 3) & 1) << 4);
                uint32_t r0, r1, r2, r3;
                LDMATRIX_X4(r0, r1, r2, r3, addr);
                bx[bt * 2 + 0][0] = r0; bx[bt * 2 + 0][1] = r1;
                bx[bt * 2 + 1][0] = r2; bx[bt * 2 + 1][1] = r3;
            }
#pragma unroll
            for (int mt = 0; mt < 4; mt++)
#pragma unroll
                for (int nt = 0; nt < 8; nt++)
                    MMA16816(accV[mt][nt], aw[mt], bx[nt]);
        }
    }

    const float* biasS = (const float*)(smq + BI_OFF);

    {
        int rq = n0 + wid * 16 + (lane >> 2);
#pragma unroll
        for (int nt = 0; nt < 8; nt++) {
            int r = nt * 8 + (lane & 3) * 2;
            float b0 = biasS[r], b1 = biasS[r + 1];
            __nv_bfloat162 pA = __floats2bfloat162_rn(accQ[nt][0] + b0,
                                                      accQ[nt][1] + b1);
            __nv_bfloat162 pB = __floats2bfloat162_rn(accQ[nt][2] + b0,
                                                      accQ[nt][3] + b1);
            if (nt < 4) {
                *(uint32_t*)&g_qT[b][rq][r]     = *(uint32_t*)&pA;
                *(uint32_t*)&g_qT[b][rq + 8][r] = *(uint32_t*)&pB;
            } else {
                *(uint32_t*)&g_kT[b][rq][r - 32]     = *(uint32_t*)&pA;
                *(uint32_t*)&g_kT[b][rq + 8][r - 32] = *(uint32_t*)&pB;
            }
        }
    }

#pragma unroll
    for (int mt = 0; mt < 4; mt++) {
        int vr = mw * 64 + mt * 16 + (lane >> 2);
        float b0 = biasS[64 + vr], b1 = biasS[64 + vr + 8];
#pragma unroll
        for (int nt = 0; nt < 8; nt++) {
            int col = n0 + nw * 64 + nt * 8 + (lane & 3) * 2;
            __nv_bfloat162 pA = __floats2bfloat162_rn(accV[mt][nt][0] + b0,
                                                      accV[mt][nt][1] + b0);
            __nv_bfloat162 pB = __floats2bfloat162_rn(accV[mt][nt][2] + b1,
                                                      accV[mt][nt][3] + b1);
            *(uint32_t*)&g_v16[b][vr][col]     = *(uint32_t*)&pA;
            *(uint32_t*)&g_v16[b][vr + 8][col] = *(uint32_t*)&pB;
        }
    }
}

// ---------------------------------------------------------------------------
// Kernel F (fused flash attention, HMMA), R8: 2 CTAs/SM.
//   per CTA: i-tile 128 x c-half 128; loop j chunks of 64:
//   S = q.k -> P' = exp(S) (C-frag == A-frag layout), acc += P'@V, rowsum.
// Inner loops process one 16-row B-group at a time (8/16 live frag regs
// instead of 16/32) so the 128-reg cap from launch_bounds(256,2) holds.
// ---------------------------------------------------------------------------
#define QS_OFF   0
#define KC_OFF   10240
#define KC_BUF   5120
#define VC_OFF   20480
#define VC_BUF   18432
#define SMEM_F   57344

__global__ __launch_bounds__(256, 2) void fused_attn_kernel(
    const float* __restrict__ x, const float* __restrict__ gamma_p,
    float* __restrict__ out)
{
    extern __shared__ char smem[];
    const uint32_t sb = smem_u32(smem);
    const int tid  = threadIdx.x;
    const int wid  = tid >> 5;
    const int lane = tid & 31;
    const int b  = blockIdx.z;
    const int c0 = blockIdx.y * 128;
    const int i0 = blockIdx.x * 128;
    const int mq = wid;

    auto load_chunk = [&](int chunk) {
        const int j0 = chunk * 64;
        {
            int row = tid >> 2, seg = tid & 3;
            CP_ASYNC16(sb + KC_OFF + (chunk & 1) * KC_BUF + row * 80 + seg * 16,
                       &g_kT[b][j0 + row][seg * 8]);
        }
#pragma unroll
        for (int p = 0; p < 4; p++) {
            int idx = tid + p * 256;
            int row = idx >> 3, seg = idx & 7;
            CP_ASYNC16(sb + VC_OFF + (chunk & 1) * VC_BUF + row * 144 + seg * 16,
                       &g_v16[b][c0 + row][j0 + seg * 8]);
        }
        CP_COMMIT();
    };

    {
#pragma unroll
        for (int p = 0; p < 2; p++) {
            int idx = tid + p * 256;
            int row = idx >> 2, seg = idx & 3;
            CP_ASYNC16(sb + QS_OFF + row * 80 + seg * 16, &g_qT[b][i0 + row][seg * 8]);
        }
    }
    load_chunk(0);

    float acc[16][4];
#pragma unroll
    for (int nt = 0; nt < 16; nt++)
#pragma unroll
        for (int r = 0; r < 4; r++) acc[nt][r] = 0.f;

    uint32_t qf[2][4];
    float sum0 = 0.f, sum1 = 0.f;

    for (int chunk = 0; chunk < NN / 64; chunk++) {
        if (chunk + 1 < NN / 64) { load_chunk(chunk + 1); CP_WAIT1(); }
        else                     { CP_WAIT0(); }
        __syncthreads();

        if (chunk == 0) {
#pragma unroll
            for (int ks = 0; ks < 2; ks++) {
                uint32_t addr = sb + QS_OFF + (mq * 16 + (lane & 15)) * 80
                              + ks * 32 + ((lane >> 4) << 4);
                LDMATRIX_X4(qf[ks][0], qf[ks][1], qf[ks][2], qf[ks][3], addr);
            }
        }

        // ---- S = q.k : per 16-row K group, 2 LDSM.x4 live (8 regs) ----
        const uint32_t kbuf = sb + KC_OFF + (chunk & 1) * KC_BUF;
        float cc[8][4];
#pragma unroll
        for (int nt = 0; nt < 8; nt++)
#pragma unroll
            for (int r = 0; r < 4; r++) cc[nt][r] = 0.f;

#pragma unroll
        for (int bt = 0; bt < 4; bt++) {
            const int row = bt * 16 + ((lane >> 4) << 3) + (lane & 7);
            uint32_t k0[4], k1[4];
            LDMATRIX_X4(k0[0], k0[1], k0[2], k0[3],
                        kbuf + row * 80 + (((lane >> 3) & 1) << 4));
            LDMATRIX_X4(k1[0], k1[1], k1[2], k1[3],
                        kbuf + row * 80 + 32 + (((lane >> 3) & 1) << 4));
            {
                uint32_t bfr[2];
                bfr[0] = k0[0]; bfr[1] = k0[1];
                MMA16816(cc[bt * 2 + 0], qf[0], bfr);
                bfr[0] = k1[0]; bfr[1] = k1[1];
                MMA16816(cc[bt * 2 + 0], qf[1], bfr);
                bfr[0] = k0[2]; bfr[1] = k0[3];
                MMA16816(cc[bt * 2 + 1], qf[0], bfr);
                bfr[0] = k1[2]; bfr[1] = k1[3];
                MMA16816(cc[bt * 2 + 1], qf[1], bfr);
            }
        }

        // ---- exp + rowsum + repack C-frags -> A-frags of PV mma ----
        uint32_t aP[4][4];
#pragma unroll
        for (int nt = 0; nt < 8; nt++) {
            float e0 = __expf(cc[nt][0]);
            float e1 = __expf(cc[nt][1]);
            float e2 = __expf(cc[nt][2]);
            float e3 = __expf(cc[nt][3]);
            sum0 += e0 + e1;
            sum1 += e2 + e3;
            __nv_bfloat162 pA = __floats2bfloat162_rn(e0, e1);
            __nv_bfloat162 pB = __floats2bfloat162_rn(e2, e3);
            int kk = nt >> 1;
            if ((nt & 1) == 0) { aP[kk][0] = *(uint32_t*)&pA; aP[kk][1] = *(uint32_t*)&pB; }
            else               { aP[kk][2] = *(uint32_t*)&pA; aP[kk][3] = *(uint32_t*)&pB; }
        }

        // ---- acc += P'@V : per 16-row V group, 4 LDSM.x4 live (16 regs) ----
        const uint32_t vbuf = sb + VC_OFF + (chunk & 1) * VC_BUF;
#pragma unroll
        for (int bt = 0; bt < 8; bt++) {
            const int row = bt * 16 + ((lane >> 4) << 3) + (lane & 7);
            const uint32_t raddr = vbuf + row * 144 + (((lane >> 3) & 1) << 4);
            uint32_t v0[4], v1[4], v2[4], v3[4];
            LDMATRIX_X4(v0[0], v0[1], v0[2], v0[3], raddr);
            LDMATRIX_X4(v1[0], v1[1], v1[2], v1[3], raddr + 32);
            LDMATRIX_X4(v2[0], v2[1], v2[2], v2[3], raddr + 64);
            LDMATRIX_X4(v3[0], v3[1], v3[2], v3[3], raddr + 96);
            uint32_t bfr[2];
            bfr[0] = v0[0]; bfr[1] = v0[1]; MMA16816(acc[bt * 2 + 0], aP[0], bfr);
            bfr[0] = v1[0]; bfr[1] = v1[1]; MMA16816(acc[bt * 2 + 0], aP[1], bfr);
            bfr[0] = v2[0]; bfr[1] = v2[1]; MMA16816(acc[bt * 2 + 0], aP[2], bfr);
            bfr[0] = v3[0]; bfr[1] = v3[1]; MMA16816(acc[bt * 2 + 0], aP[3], bfr);
            bfr[0] = v0[2]; bfr[1] = v0[3]; MMA16816(acc[bt * 2 + 1], aP[0], bfr);
            bfr[0] = v1[2]; bfr[1] = v1[3]; MMA16816(acc[bt * 2 + 1], aP[1], bfr);
            bfr[0] = v2[2]; bfr[1] = v2[3]; MMA16816(acc[bt * 2 + 1], aP[2], bfr);
            bfr[0] = v3[2]; bfr[1] = v3[3]; MMA16816(acc[bt * 2 + 1], aP[3], bfr);
        }
        __syncthreads();
    }

    sum0 += __shfl_xor_sync(0xffffffffu, sum0, 1);
    sum0 += __shfl_xor_sync(0xffffffffu, sum0, 2);
    sum1 += __shfl_xor_sync(0xffffffffu, sum1, 1);
    sum1 += __shfl_xor_sync(0xffffffffu, sum1, 2);
    const float inv0 = 1.0f / sum0;
    const float inv1 = 1.0f / sum1;
#pragma unroll
    for (int nt = 0; nt < 16; nt++) {
        acc[nt][0] *= inv0; acc[nt][1] *= inv0;
        acc[nt][2] *= inv1; acc[nt][3] *= inv1;
    }

    const float gam = gamma_p[0];
    const int g2 = lane >> 2;
    const int tg = lane & 3;
    const int irow = i0 + mq * 16 + g2;
#pragma unroll
    for (int nt = 0; nt < 16; nt++) {
        int c = c0 + nt * 8 + tg * 2;
        size_t o00 = ((size_t)(b * CC_ + c)) * NN + irow;
        size_t o10 = o00 + NN;
        out[o00]     = fmaf(gam, acc[nt][0], x[o00]);
        out[o10]     = fmaf(gam, acc[nt][1], x[o10]);
        out[o00 + 8] = fmaf(gam, acc[nt][2], x[o00 + 8]);
        out[o10 + 8] = fmaf(gam, acc[nt][3], x[o10 + 8]);
    }
}

// ---------------------------------------------------------------------------
extern "C" void kernel_launch(void* const* d_in, const int* in_sizes, int n_in,
                              void* d_out, int out_size)
{
    const float* x     = (const float*)d_in[0];
    const float* wq    = (const float*)d_in[1];
    const float* bq    = (const float*)d_in[2];
    const float* wk    = (const float*)d_in[3];
    const float* bk    = (const float*)d_in[4];
    const float* wv    = (const float*)d_in[5];
    const float* bv    = (const float*)d_in[6];
    const float* gamma = (const float*)d_in[7];
    float* out = (float*)d_out;

    cudaFuncSetAttribute(qkv_hmma_kernel,
                         cudaFuncAttributeMaxDynamicSharedMemorySize, SMEM_Q);
    cudaFuncSetAttribute(fused_attn_kernel,
                         cudaFuncAttributeMaxDynamicSharedMemorySize, SMEM_F);

    wconv_kernel<<<dim3(320), 256>>>(wq, bq, wk, bk, wv, bv);
    qkv_hmma_kernel<<<dim3(32, 4), 256, SMEM_Q>>>(x);
    fused_attn_kernel<<<dim3(32, 2, 4), 256, SMEM_F>>>(x, gamma, out);
}

// round 10
// speedup vs baseline: 8.4599x; 1.1404x over previous
#include <cuda_runtime.h>
#include <cuda_bf16.h>
#include <cstdint>

// Self_Attention: x[B,C,H,W], 1x1-conv projections q,k (D=32), v (C),
// energy = q^T k, softmax over j, out = V @ attn^T, final = gamma*out + x.
// Plain-sm_103 PTX target -> no tcgen05; HMMA (mma.sync) + ldmatrix + cp.async.
// R9: fused_attn widened to c-full 256 per CTA at (256,1)/255 regs: no spill,
// S/exp/K work no longer duplicated across c-half CTAs, 2x MMA per chunk.
#define BB 4
#define CC_ 256
#define NN 4096
#define DD 32

// Scratch (device globals; no runtime allocation allowed)
__device__ __nv_bfloat16 g_v16[BB][CC_][NN];   // V bf16, 8 MB
__device__ __nv_bfloat16 g_qT[BB][NN][DD];     // q bf16 token-major, 1 MB
__device__ __nv_bfloat16 g_kT[BB][NN][DD];     // k bf16 token-major, 1 MB
__device__ __nv_bfloat16 g_w16[320][CC_];      // W bf16 (q,k,v stacked), 160 KB
__device__ float g_biasf[320];                 // biases (q,k,v stacked)

__device__ __forceinline__ uint32_t smem_u32(const void* p) {
    uint32_t a;
    asm("{ .reg .u64 t; cvta.to.shared.u64 t, %1; cvt.u32.u64 %0, t; }" : "=r"(a) : "l"(p));
    return a;
}

#define CP_ASYNC16(dst, src) \
    asm volatile("cp.async.cg.shared.global [%0], [%1], 16;" :: "r"(dst), "l"(src))
#define CP_COMMIT()  asm volatile("cp.async.commit_group;")
#define CP_WAIT1()   asm volatile("cp.async.wait_group 1;")
#define CP_WAIT0()   asm volatile("cp.async.wait_group 0;")

#define LDMATRIX_X4(r0, r1, r2, r3, addr)                                          \
    asm volatile("ldmatrix.sync.aligned.m8n8.x4.shared.b16 {%0,%1,%2,%3}, [%4];"   \
        : "=r"(r0), "=r"(r1), "=r"(r2), "=r"(r3) : "r"(addr))

#define MMA16816(c, a, b)                                                          \
    asm volatile("mma.sync.aligned.m16n8k16.row.col.f32.bf16.bf16.f32 "            \
        "{%0,%1,%2,%3}, {%4,%5,%6,%7}, {%8,%9}, {%0,%1,%2,%3};"                    \
        : "+f"((c)[0]), "+f"((c)[1]), "+f"((c)[2]), "+f"((c)[3])                   \
        : "r"((a)[0]), "r"((a)[1]), "r"((a)[2]), "r"((a)[3]),                      \
          "r"((b)[0]), "r"((b)[1]))

// ---------------------------------------------------------------------------
// Kernel W: convert weights to bf16 (rows 0-31 q, 32-63 k, 64-319 v) + biases.
// ---------------------------------------------------------------------------
__global__ __launch_bounds__(256) void wconv_kernel(
    const float* __restrict__ wq, const float* __restrict__ bq,
    const float* __restrict__ wk, const float* __restrict__ bk,
    const float* __restrict__ wv, const float* __restrict__ bv)
{
    const int row = blockIdx.x;
    const int t = threadIdx.x;
    const float* src = row < 32 ? wq + row * CC_
                     : row < 64 ? wk + (row - 32) * CC_
                                : wv + (row - 64) * CC_;
    g_w16[row][t] = __float2bfloat16(src[t]);
    if (t == 0)
        g_biasf[row] = row < 32 ? bq[row] : row < 64 ? bk[row - 32] : bv[row - 64];
}

// ---------------------------------------------------------------------------
// Kernel A (HMMA QKV): unchanged from R7.
// ---------------------------------------------------------------------------
#define WROW    528
#define WS_OFF  0
#define XROW    144
#define XS_OFF  168960
#define BI_OFF  (168960 + 18432)
#define SMEM_Q  (168960 + 18432 + 1280)

__global__ __launch_bounds__(256, 1) void qkv_hmma_kernel(
    const float* __restrict__ x)
{
    extern __shared__ char smq[];
    const uint32_t sb = smem_u32(smq);
    const int tid  = threadIdx.x;
    const int wid  = tid >> 5;
    const int lane = tid & 31;
    const int b  = blockIdx.y;
    const int n0 = blockIdx.x * 128;

#pragma unroll
    for (int p = 0; p < 40; p++) {
        int idx = tid + p * 256;
        int row = idx >> 5, seg = idx & 31;
        CP_ASYNC16(sb + WS_OFF + row * WROW + seg * 16, &g_w16[row][seg * 8]);
    }
    if (tid < 80) CP_ASYNC16(sb + BI_OFF + tid * 16, &g_biasf[tid * 4]);
    CP_COMMIT();

    float accQ[8][4];
    float accV[4][8][4];
#pragma unroll
    for (int nt = 0; nt < 8; nt++)
#pragma unroll
        for (int r = 0; r < 4; r++) accQ[nt][r] = 0.f;
#pragma unroll
    for (int mt = 0; mt < 4; mt++)
#pragma unroll
        for (int nt = 0; nt < 8; nt++)
#pragma unroll
            for (int r = 0; r < 4; r++) accV[mt][nt][r] = 0.f;

    const int mw = wid >> 1;
    const int nw = wid & 1;
    const int ntok = tid & 127;
    const int cgrp = (tid >> 7) * 32;

    float xr[32];
    {
        const float* xp = x + ((size_t)(b * CC_ + cgrp)) * NN + n0 + ntok;
#pragma unroll
        for (int q = 0; q < 32; q++) xr[q] = xp[(size_t)q * NN];
    }

    for (int ck = 0; ck < 4; ck++) {
        __syncthreads();
#pragma unroll
        for (int q = 0; q < 16; q++) {
            __nv_bfloat162 pk = __floats2bfloat162_rn(xr[2 * q], xr[2 * q + 1]);
            *(uint32_t*)(smq + XS_OFF + ntok * XROW + (cgrp + 2 * q) * 2) =
                *(uint32_t*)&pk;
        }
        if (ck == 0) CP_WAIT0();
        __syncthreads();

        if (ck < 3) {
            const float* xp = x + ((size_t)(b * CC_ + (ck + 1) * 64 + cgrp)) * NN
                            + n0 + ntok;
#pragma unroll
            for (int q = 0; q < 32; q++) xr[q] = xp[(size_t)q * NN];
        }

        const uint32_t wbase = sb + WS_OFF + ck * 128;
#pragma unroll
        for (int ks = 0; ks < 4; ks++) {
            const int kb = ks * 32;
            uint32_t ax[4];
            {
                uint32_t addr = sb + XS_OFF + (wid * 16 + (lane & 15)) * XROW
                              + kb + ((lane >> 4) << 4);
                LDMATRIX_X4(ax[0], ax[1], ax[2], ax[3], addr);
            }
            uint32_t bw[8][2];
#pragma unroll
            for (int bt = 0; bt < 4; bt++) {
                int row = bt * 16 + ((lane >> 4) << 3) + (lane & 7);
                uint32_t addr = wbase + row * WROW + kb + (((lane >> 3) & 1) << 4);
                uint32_t r0, r1, r2, r3;
                LDMATRIX_X4(r0, r1, r2, r3, addr);
                bw[bt * 2 + 0][0] = r0; bw[bt * 2 + 0][1] = r1;
                bw[bt * 2 + 1][0] = r2; bw[bt * 2 + 1][1] = r3;
            }
#pragma unroll
            for (int nt = 0; nt < 8; nt++) MMA16816(accQ[nt], ax, bw[nt]);

            uint32_t aw[4][4];
#pragma unroll
            for (int mt = 0; mt < 4; mt++) {
                uint32_t addr = wbase + (64 + mw * 64 + mt * 16 + (lane & 15)) * WROW
                              + kb + ((lane >> 4) << 4);
                LDMATRIX_X4(aw[mt][0], aw[mt][1], aw[mt][2], aw[mt][3], addr);
            }
            uint32_t bx[8][2];
#pragma unroll
            for (int bt = 0; bt < 4; bt++) {
                int row = nw * 64 + bt * 16 + ((lane >> 4) << 3) + (lane & 7);
                uint32_t addr = sb + XS_OFF + row * XROW + kb
                              + (((lane >> 3) & 1) << 4);
                uint32_t r0, r1, r2, r3;
                LDMATRIX_X4(r0, r1, r2, r3, addr);
                bx[bt * 2 + 0][0] = r0; bx[bt * 2 + 0][1] = r1;
                bx[bt * 2 + 1][0] = r2; bx[bt * 2 + 1][1] = r3;
            }
#pragma unroll
            for (int mt = 0; mt < 4; mt++)
#pragma unroll
                for (int nt = 0; nt < 8; nt++)
                    MMA16816(accV[mt][nt], aw[mt], bx[nt]);
        }
    }

    const float* biasS = (const float*)(smq + BI_OFF);

    {
        int rq = n0 + wid * 16 + (lane >> 2);
#pragma unroll
        for (int nt = 0; nt < 8; nt++) {
            int r = nt * 8 + (lane & 3) * 2;
            float b0 = biasS[r], b1 = biasS[r + 1];
            __nv_bfloat162 pA = __floats2bfloat162_rn(accQ[nt][0] + b0,
                                                      accQ[nt][1] + b1);
            __nv_bfloat162 pB = __floats2bfloat162_rn(accQ[nt][2] + b0,
                                                      accQ[nt][3] + b1);
            if (nt < 4) {
                *(uint32_t*)&g_qT[b][rq][r]     = *(uint32_t*)&pA;
                *(uint32_t*)&g_qT[b][rq + 8][r] = *(uint32_t*)&pB;
            } else {
                *(uint32_t*)&g_kT[b][rq][r - 32]     = *(uint32_t*)&pA;
                *(uint32_t*)&g_kT[b][rq + 8][r - 32] = *(uint32_t*)&pB;
            }
        }
    }

#pragma unroll
    for (int mt = 0; mt < 4; mt++) {
        int vr = mw * 64 + mt * 16 + (lane >> 2);
        float b0 = biasS[64 + vr], b1 = biasS[64 + vr + 8];
#pragma unroll
        for (int nt = 0; nt < 8; nt++) {
            int col = n0 + nw * 64 + nt * 8 + (lane & 3) * 2;
            __nv_bfloat162 pA = __floats2bfloat162_rn(accV[mt][nt][0] + b0,
                                                      accV[mt][nt][1] + b0);
            __nv_bfloat162 pB = __floats2bfloat162_rn(accV[mt][nt][2] + b1,
                                                      accV[mt][nt][3] + b1);
            *(uint32_t*)&g_v16[b][vr][col]     = *(uint32_t*)&pA;
            *(uint32_t*)&g_v16[b][vr + 8][col] = *(uint32_t*)&pB;
        }
    }
}

// ---------------------------------------------------------------------------
// Kernel F (fused flash attention, HMMA), R9: c-full 256 per CTA, (256,1).
//   per CTA: i-tile 128 x ALL 256 channels; loop j chunks of 64:
//   S = q.k (once -- no c-half duplication) -> P' = exp(S) -> acc += P'@V.
//   acc = 32 ntiles x 4 = 128 regs/thread; total live ~200 regs, no spill.
// grid (32 i, 4 b) = 128 CTAs, 256 threads, 94208 B dyn smem.
// ---------------------------------------------------------------------------
#define QS_OFF   0
#define KC_OFF   10240
#define KC_BUF   5120
#define VC_OFF   20480
#define VC_BUF   36864
#define SMEM_F   94208

__global__ __launch_bounds__(256, 1) void fused_attn_kernel(
    const float* __restrict__ x, const float* __restrict__ gamma_p,
    float* __restrict__ out)
{
    extern __shared__ char smem[];
    const uint32_t sb = smem_u32(smem);
    const int tid  = threadIdx.x;
    const int wid  = tid >> 5;
    const int lane = tid & 31;
    const int b  = blockIdx.y;
    const int i0 = blockIdx.x * 128;
    const int mq = wid;

    auto load_chunk = [&](int chunk) {
        const int j0 = chunk * 64;
        // K: 64 rows x 4 segs = 256 transfers, 1/thread
        {
            int row = tid >> 2, seg = tid & 3;
            CP_ASYNC16(sb + KC_OFF + (chunk & 1) * KC_BUF + row * 80 + seg * 16,
                       &g_kT[b][j0 + row][seg * 8]);
        }
        // V: 256 rows x 8 segs = 2048 transfers, 8/thread
#pragma unroll
        for (int p = 0; p < 8; p++) {
            int idx = tid + p * 256;
            int row = idx >> 3, seg = idx & 7;
            CP_ASYNC16(sb + VC_OFF + (chunk & 1) * VC_BUF + row * 144 + seg * 16,
                       &g_v16[b][row][j0 + seg * 8]);
        }
        CP_COMMIT();
    };

    {
#pragma unroll
        for (int p = 0; p < 2; p++) {
            int idx = tid + p * 256;
            int row = idx >> 2, seg = idx & 3;
            CP_ASYNC16(sb + QS_OFF + row * 80 + seg * 16, &g_qT[b][i0 + row][seg * 8]);
        }
    }
    load_chunk(0);

    float acc[32][4];
#pragma unroll
    for (int nt = 0; nt < 32; nt++)
#pragma unroll
        for (int r = 0; r < 4; r++) acc[nt][r] = 0.f;

    uint32_t qf[2][4];
    float sum0 = 0.f, sum1 = 0.f;

    for (int chunk = 0; chunk < NN / 64; chunk++) {
        if (chunk + 1 < NN / 64) { load_chunk(chunk + 1); CP_WAIT1(); }
        else                     { CP_WAIT0(); }
        __syncthreads();

        if (chunk == 0) {
#pragma unroll
            for (int ks = 0; ks < 2; ks++) {
                uint32_t addr = sb + QS_OFF + (mq * 16 + (lane & 15)) * 80
                              + ks * 32 + ((lane >> 4) << 4);
                LDMATRIX_X4(qf[ks][0], qf[ks][1], qf[ks][2], qf[ks][3], addr);
            }
        }

        // ---- S = q.k : per 16-row K group, 2 LDSM.x4 live ----
        const uint32_t kbuf = sb + KC_OFF + (chunk & 1) * KC_BUF;
        float cc[8][4];
#pragma unroll
        for (int nt = 0; nt < 8; nt++)
#pragma unroll
            for (int r = 0; r < 4; r++) cc[nt][r] = 0.f;

#pragma unroll
        for (int bt = 0; bt < 4; bt++) {
            const int row = bt * 16 + ((lane >> 4) << 3) + (lane & 7);
            uint32_t k0[4], k1[4];
            LDMATRIX_X4(k0[0], k0[1], k0[2], k0[3],
                        kbuf + row * 80 + (((lane >> 3) & 1) << 4));
            LDMATRIX_X4(k1[0], k1[1], k1[2], k1[3],
                        kbuf + row * 80 + 32 + (((lane >> 3) & 1) << 4));
            {
                uint32_t bfr[2];
                bfr[0] = k0[0]; bfr[1] = k0[1];
                MMA16816(cc[bt * 2 + 0], qf[0], bfr);
                bfr[0] = k1[0]; bfr[1] = k1[1];
                MMA16816(cc[bt * 2 + 0], qf[1], bfr);
                bfr[0] = k0[2]; bfr[1] = k0[3];
                MMA16816(cc[bt * 2 + 1], qf[0], bfr);
                bfr[0] = k1[2]; bfr[1] = k1[3];
                MMA16816(cc[bt * 2 + 1], qf[1], bfr);
            }
        }

        // ---- exp + rowsum + repack C-frags -> A-frags of PV mma ----
        uint32_t aP[4][4];
#pragma unroll
        for (int nt = 0; nt < 8; nt++) {
            float e0 = __expf(cc[nt][0]);
            float e1 = __expf(cc[nt][1]);
            float e2 = __expf(cc[nt][2]);
            float e3 = __expf(cc[nt][3]);
            sum0 += e0 + e1;
            sum1 += e2 + e3;
            __nv_bfloat162 pA = __floats2bfloat162_rn(e0, e1);
            __nv_bfloat162 pB = __floats2bfloat162_rn(e2, e3);
            int kk = nt >> 1;
            if ((nt & 1) == 0) { aP[kk][0] = *(uint32_t*)&pA; aP[kk][1] = *(uint32_t*)&pB; }
            else               { aP[kk][2] = *(uint32_t*)&pA; aP[kk][3] = *(uint32_t*)&pB; }
        }

        // ---- acc += P'@V over 256 V rows: per 16-row group, 4 LDSM live ----
        const uint32_t vbuf = sb + VC_OFF + (chunk & 1) * VC_BUF;
#pragma unroll
        for (int bt = 0; bt < 16; bt++) {
            const int row = bt * 16 + ((lane >> 4) << 3) + (lane & 7);
            const uint32_t raddr = vbuf + row * 144 + (((lane >> 3) & 1) << 4);
            uint32_t v0[4], v1[4], v2[4], v3[4];
            LDMATRIX_X4(v0[0], v0[1], v0[2], v0[3], raddr);
            LDMATRIX_X4(v1[0], v1[1], v1[2], v1[3], raddr + 32);
            LDMATRIX_X4(v2[0], v2[1], v2[2], v2[3], raddr + 64);
            LDMATRIX_X4(v3[0], v3[1], v3[2], v3[3], raddr + 96);
            uint32_t bfr[2];
            bfr[0] = v0[0]; bfr[1] = v0[1]; MMA16816(acc[bt * 2 + 0], aP[0], bfr);
            bfr[0] = v1[0]; bfr[1] = v1[1]; MMA16816(acc[bt * 2 + 0], aP[1], bfr);
            bfr[0] = v2[0]; bfr[1] = v2[1]; MMA16816(acc[bt * 2 + 0], aP[2], bfr);
            bfr[0] = v3[0]; bfr[1] = v3[1]; MMA16816(acc[bt * 2 + 0], aP[3], bfr);
            bfr[0] = v0[2]; bfr[1] = v0[3]; MMA16816(acc[bt * 2 + 1], aP[0], bfr);
            bfr[0] = v1[2]; bfr[1] = v1[3]; MMA16816(acc[bt * 2 + 1], aP[1], bfr);
            bfr[0] = v2[2]; bfr[1] = v2[3]; MMA16816(acc[bt * 2 + 1], aP[2], bfr);
            bfr[0] = v3[2]; bfr[1] = v3[3]; MMA16816(acc[bt * 2 + 1], aP[3], bfr);
        }
        __syncthreads();
    }

    sum0 += __shfl_xor_sync(0xffffffffu, sum0, 1);
    sum0 += __shfl_xor_sync(0xffffffffu, sum0, 2);
    sum1 += __shfl_xor_sync(0xffffffffu, sum1, 1);
    sum1 += __shfl_xor_sync(0xffffffffu, sum1, 2);
    const float inv0 = 1.0f / sum0;
    const float inv1 = 1.0f / sum1;
#pragma unroll
    for (int nt = 0; nt < 32; nt++) {
        acc[nt][0] *= inv0; acc[nt][1] *= inv0;
        acc[nt][2] *= inv1; acc[nt][3] *= inv1;
    }

    const float gam = gamma_p[0];
    const int g2 = lane >> 2;
    const int tg = lane & 3;
    const int irow = i0 + mq * 16 + g2;
#pragma unroll
    for (int nt = 0; nt < 32; nt++) {
        int c = nt * 8 + tg * 2;
        size_t o00 = ((size_t)(b * CC_ + c)) * NN + irow;
        size_t o10 = o00 + NN;
        out[o00]     = fmaf(gam, acc[nt][0], x[o00]);
        out[o10]     = fmaf(gam, acc[nt][1], x[o10]);
        out[o00 + 8] = fmaf(gam, acc[nt][2], x[o00 + 8]);
        out[o10 + 8] = fmaf(gam, acc[nt][3], x[o10 + 8]);
    }
}

// ---------------------------------------------------------------------------
extern "C" void kernel_launch(void* const* d_in, const int* in_sizes, int n_in,
                              void* d_out, int out_size)
{
    const float* x     = (const float*)d_in[0];
    const float* wq    = (const float*)d_in[1];
    const float* bq    = (const float*)d_in[2];
    const float* wk    = (const float*)d_in[3];
    const float* bk    = (const float*)d_in[4];
    const float* wv    = (const float*)d_in[5];
    const float* bv    = (const float*)d_in[6];
    const float* gamma = (const float*)d_in[7];
    float* out = (float*)d_out;

    cudaFuncSetAttribute(qkv_hmma_kernel,
                         cudaFuncAttributeMaxDynamicSharedMemorySize, SMEM_Q);
    cudaFuncSetAttribute(fused_attn_kernel,
                         cudaFuncAttributeMaxDynamicSharedMemorySize, SMEM_F);

    wconv_kernel<<<dim3(320), 256>>>(wq, bq, wk, bk, wv, bv);
    qkv_hmma_kernel<<<dim3(32, 4), 256, SMEM_Q>>>(x);
    fused_attn_kernel<<<dim3(32, 4), 256, SMEM_F>>>(x, gamma, out);
}